// round 2
// baseline (speedup 1.0000x reference)
#include <cuda_runtime.h>
#include <math.h>

#define CS 1024
#define NH 16
#define HD 64

// ---------------- scratch (static device globals; no runtime allocation) ----
__device__ float g_q[1024 * 1024];
__device__ float g_k[1024 * 1024];
__device__ float g_v[1024 * 1024];
__device__ float g_g[1024 * 1024];
__device__ float g_tmp[1024 * 1024];
__device__ float g_z[16 * 1024 * 1024];   // [h][i][j]

// ---------------- packed f32x2 helpers (FFMA2 — 2x fp32 FMA throughput) -----
typedef unsigned long long u64;
__device__ __forceinline__ u64 pk2(float a, float b) {
    u64 r; asm("mov.b64 %0,{%1,%2};" : "=l"(r) : "f"(a), "f"(b)); return r;
}
__device__ __forceinline__ u64 dup2(float a) { return pk2(a, a); }
__device__ __forceinline__ float2 up2(u64 v) {
    float2 f; asm("mov.b64 {%0,%1},%2;" : "=f"(f.x), "=f"(f.y) : "l"(v)); return f;
}
__device__ __forceinline__ u64 fma2(u64 a, u64 b, u64 c) {
    u64 d; asm("fma.rn.f32x2 %0,%1,%2,%3;" : "=l"(d) : "l"(a), "l"(b), "l"(c)); return d;
}
__device__ __forceinline__ u64 mul2(u64 a, u64 b) {
    u64 d; asm("mul.rn.f32x2 %0,%1,%2;" : "=l"(d) : "l"(a), "l"(b)); return d;
}

// ---------------- GEMM body: C[M,N] = A[M,K] * B[N,K]^T (+bias / sigmoid) ----
// MODE 0: plain, 1: +bias[n], 2: sigmoid. TN must be 4 or 8.
template <int BM, int BN, int TM, int TN, int MODE>
__device__ __forceinline__ void gemm_body(const float* __restrict__ A,
                                          const float* __restrict__ B,
                                          float* __restrict__ C,
                                          const float* __restrict__ bias,
                                          float* As, float* Bs,
                                          int bm0, int bn0) {
    const int tid = threadIdx.x;
    constexpr int TNX = BN / TN;            // threads along n
    const int tx = tid % TNX;
    const int ty = tid / TNX;

    u64 acc[TM][TN / 2];
#pragma unroll
    for (int i = 0; i < TM; i++)
#pragma unroll
        for (int j = 0; j < TN / 2; j++) acc[i][j] = 0ull;

    for (int k0 = 0; k0 < CS; k0 += 8) {
        __syncthreads();
        if (tid < BM * 2) {
            int row = tid >> 1, ko = (tid & 1) * 4;
            float4 v = *(const float4*)(A + (size_t)(bm0 + row) * CS + k0 + ko);
            As[(ko + 0) * BM + row] = v.x;
            As[(ko + 1) * BM + row] = v.y;
            As[(ko + 2) * BM + row] = v.z;
            As[(ko + 3) * BM + row] = v.w;
        }
        if (tid < BN * 2) {
            int row = tid >> 1, ko = (tid & 1) * 4;
            float4 v = *(const float4*)(B + (size_t)(bn0 + row) * CS + k0 + ko);
            Bs[(ko + 0) * BN + row] = v.x;
            Bs[(ko + 1) * BN + row] = v.y;
            Bs[(ko + 2) * BN + row] = v.z;
            Bs[(ko + 3) * BN + row] = v.w;
        }
        __syncthreads();
#pragma unroll
        for (int kk = 0; kk < 8; kk++) {
            float a[TM];
            u64 b2[TN / 2];
#pragma unroll
            for (int i = 0; i < TM; i += 4)
                *(float4*)&a[i] = *(const float4*)&As[kk * BM + ty * TM + i];
            if constexpr (TN == 8) {
                // split-B fragment: two 16B chunks -> conflict-free LDS.128
                float4 blo = *(const float4*)&Bs[kk * BN + tx * 4];
                float4 bhi = *(const float4*)&Bs[kk * BN + BN / 2 + tx * 4];
                b2[0] = pk2(blo.x, blo.y); b2[1] = pk2(blo.z, blo.w);
                b2[2] = pk2(bhi.x, bhi.y); b2[3] = pk2(bhi.z, bhi.w);
            } else {
                float4 bb = *(const float4*)&Bs[kk * BN + tx * 4];
                b2[0] = pk2(bb.x, bb.y); b2[1] = pk2(bb.z, bb.w);
            }
#pragma unroll
            for (int i = 0; i < TM; i++) {
                u64 a2 = dup2(a[i]);
#pragma unroll
                for (int j = 0; j < TN / 2; j++) acc[i][j] = fma2(a2, b2[j], acc[i][j]);
            }
        }
    }

    // epilogue (vectorized STG.128)
    float4 bia_lo = make_float4(0.f, 0.f, 0.f, 0.f), bia_hi = bia_lo;
    if constexpr (MODE == 1) {
        bia_lo = *(const float4*)(bias + bn0 + tx * 4);
        if constexpr (TN == 8) bia_hi = *(const float4*)(bias + bn0 + BN / 2 + tx * 4);
    }
#pragma unroll
    for (int i = 0; i < TM; i++) {
        size_t m = (size_t)(bm0 + ty * TM + i);
        float2 p0 = up2(acc[i][0]), p1 = up2(acc[i][1]);
        float4 lo = make_float4(p0.x, p0.y, p1.x, p1.y);
        if constexpr (MODE == 1) {
            lo.x += bia_lo.x; lo.y += bia_lo.y; lo.z += bia_lo.z; lo.w += bia_lo.w;
        }
        if constexpr (MODE == 2) {
            lo.x = 1.f / (1.f + __expf(-lo.x)); lo.y = 1.f / (1.f + __expf(-lo.y));
            lo.z = 1.f / (1.f + __expf(-lo.z)); lo.w = 1.f / (1.f + __expf(-lo.w));
        }
        *(float4*)(C + m * CS + bn0 + tx * 4) = lo;
        if constexpr (TN == 8) {
            float2 p2 = up2(acc[i][2]), p3 = up2(acc[i][3]);
            float4 hi = make_float4(p2.x, p2.y, p3.x, p3.y);
            if constexpr (MODE == 1) {
                hi.x += bia_hi.x; hi.y += bia_hi.y; hi.z += bia_hi.z; hi.w += bia_hi.w;
            }
            if constexpr (MODE == 2) {
                hi.x = 1.f / (1.f + __expf(-hi.x)); hi.y = 1.f / (1.f + __expf(-hi.y));
                hi.z = 1.f / (1.f + __expf(-hi.z)); hi.w = 1.f / (1.f + __expf(-hi.w));
            }
            *(float4*)(C + m * CS + bn0 + BN / 2 + tx * 4) = hi;
        }
    }
}

// ---------------- fused projections: q,k,v,g in one launch ------------------
__global__ __launch_bounds__(256) void proj_kernel(const float* __restrict__ s,
                                                   const float* __restrict__ kin,
                                                   const float* __restrict__ Wq,
                                                   const float* __restrict__ bq,
                                                   const float* __restrict__ Wk,
                                                   const float* __restrict__ Wv,
                                                   const float* __restrict__ Wg) {
    __shared__ float As[8 * 128];
    __shared__ float Bs[8 * 128];
    const int bm0 = blockIdx.y * 128;
    const int bn0 = blockIdx.x * 128;
    switch (blockIdx.z) {
        case 0: gemm_body<128, 128, 8, 8, 1>(s,   Wq, g_q, bq,      As, Bs, bm0, bn0); break;
        case 1: gemm_body<128, 128, 8, 8, 0>(kin, Wk, g_k, nullptr, As, Bs, bm0, bn0); break;
        case 2: gemm_body<128, 128, 8, 8, 0>(kin, Wv, g_v, nullptr, As, Bs, bm0, bn0); break;
        default: gemm_body<128, 128, 8, 8, 2>(s,  Wg, g_g, nullptr, As, Bs, bm0, bn0); break;
    }
}

// ---------------- output GEMM: out = (g*o) @ Wo^T ---------------------------
// 128x64 tiles -> 128-block grid (~one full wave on 148 SMs)
__global__ __launch_bounds__(256) void out_kernel(const float* __restrict__ Wo,
                                                  float* __restrict__ out) {
    __shared__ float As[8 * 128];
    __shared__ float Bs[8 * 64];
    gemm_body<128, 64, 8, 4, 0>(g_tmp, Wo, out, nullptr, As, Bs,
                                blockIdx.y * 128, blockIdx.x * 64);
}

// ---------------- pair-bias projection z[h][i][j] + mask --------------------
// z = bias[i,j,:] @ Wz[:,h]  + (1-mask[j]) * (-1e6)
__global__ __launch_bounds__(64) void z_kernel(const float* __restrict__ bias,
                                               const float* __restrict__ Wz,
                                               const float* __restrict__ mask) {
    __shared__ float sb[64 * 132];     // 64 pairs x 128 (stride 132: bank-clean)
    __shared__ float swz[128 * 16];    // Wz [c][h]
    const int tid = threadIdx.x;
    const size_t p0 = (size_t)blockIdx.x * 64;

    for (int idx = tid; idx < 128 * 16; idx += 64) swz[idx] = Wz[idx];
#pragma unroll
    for (int u = 0; u < 32; u++) {
        int lin = tid + u * 64;          // float4 index within block tile
        int pr = lin >> 5;               // pair row (0..63)
        int pc = (lin & 31) << 2;        // float column
        float4 v = *(const float4*)(bias + ((p0 + pr) << 7) + pc);
        *(float4*)&sb[pr * 132 + pc] = v;
    }
    __syncthreads();

    const int hg = tid & 3;              // head group: h = hg*4 + q
    const int pg = tid >> 2;             // pair group: pairs pg + 16*i
    u64 acc[4][2];
#pragma unroll
    for (int i = 0; i < 4; i++) { acc[i][0] = 0ull; acc[i][1] = 0ull; }

#pragma unroll 4
    for (int c = 0; c < 128; c++) {
        float4 w = *(const float4*)&swz[c * 16 + hg * 4];
        u64 w01 = pk2(w.x, w.y), w23 = pk2(w.z, w.w);
#pragma unroll
        for (int i = 0; i < 4; i++) {
            u64 bv = dup2(sb[(pg + 16 * i) * 132 + c]);
            acc[i][0] = fma2(bv, w01, acc[i][0]);
            acc[i][1] = fma2(bv, w23, acc[i][1]);
        }
    }

#pragma unroll
    for (int i = 0; i < 4; i++) {
        size_t pair = p0 + pg + 16 * i;
        int j = (int)(pair & 1023);
        float madd = (1.f - mask[j]) * (-1000000.f);
        float2 a0 = up2(acc[i][0]), a1 = up2(acc[i][1]);
        float zv[4] = {a0.x, a0.y, a1.x, a1.y};
#pragma unroll
        for (int q = 0; q < 4; q++) {
            int hh = hg * 4 + q;
            g_z[(size_t)hh * 1048576 + pair] = zv[q] + madd;
        }
    }
}

// ---------------- flash attention + fused gating ----------------------------
// grid (16 i-blocks, 16 heads), 256 threads. BM=64 queries, BN=64 keys, D=64.
// Q/K in smem transposed [d][c] with XOR-(d>>2) swizzle of the 16B column
// group -> conflict-free transpose stores AND conflict-free float4 reads.
__global__ __launch_bounds__(256) void attn_kernel() {
    extern __shared__ float sm[];
    float* Qt = sm;                // 64*64  (swizzled, [d][r])
    float* Kt = sm + 4096;         // 64*64  (swizzled, [d][c])
    float* Vs = sm + 8192;         // 64*64  ([j][d], natural)
    float* Ps = sm + 12288;        // 64*68  ([r][j], pad 68)

    const int tid = threadIdx.x;
    const int tx = tid & 15;       // d-column group for O / key group for S
    const int ty = tid >> 4;       // query-row group
    const int h = blockIdx.y;
    const int i0 = blockIdx.x * 64;
    const int colbase = h * 64;

    // load Q transposed+swizzled
#pragma unroll
    for (int u = 0; u < 4; u++) {
        int lin = tid + u * 256;                 // float4 id 0..1023
        int r = lin >> 4;
        int d4 = lin & 15;
        float4 v = *(const float4*)(g_q + (size_t)(i0 + r) * CS + colbase + (d4 << 2));
        int grp = ((r >> 2) ^ d4) & 15;
        float* p = Qt + ((d4 << 2) << 6) + (grp << 2) + (r & 3);
        p[0] = v.x; p[64] = v.y; p[128] = v.z; p[192] = v.w;
    }

    float m[4], l[4];
    u64 O2[4][2];
#pragma unroll
    for (int i = 0; i < 4; i++) {
        m[i] = -1e30f; l[i] = 0.f;
        O2[i][0] = 0ull; O2[i][1] = 0ull;
    }

    for (int j0 = 0; j0 < 1024; j0 += 64) {
        __syncthreads();   // prior PV done before overwriting K/V/P
#pragma unroll
        for (int u = 0; u < 4; u++) {
            int lin = tid + u * 256;
            int r = lin >> 4;
            int d4 = lin & 15;
            float4 kv = *(const float4*)(g_k + (size_t)(j0 + r) * CS + colbase + (d4 << 2));
            int grp = ((r >> 2) ^ d4) & 15;
            float* p = Kt + ((d4 << 2) << 6) + (grp << 2) + (r & 3);
            p[0] = kv.x; p[64] = kv.y; p[128] = kv.z; p[192] = kv.w;
            float4 vv = *(const float4*)(g_v + (size_t)(j0 + r) * CS + colbase + (d4 << 2));
            *(float4*)&Vs[r * 64 + (d4 << 2)] = vv;
        }
        __syncthreads();

        // S = Q K^T  (64 x 64 tile, 4x4 per thread, packed f32x2 over keys)
        u64 S2[4][2];
#pragma unroll
        for (int i = 0; i < 4; i++) { S2[i][0] = 0ull; S2[i][1] = 0ull; }

#pragma unroll 4
        for (int dg = 0; dg < 16; dg++) {
            const int qg = ((ty ^ dg) & 15) << 2;
            const int kg = ((tx ^ dg) & 15) << 2;
#pragma unroll
            for (int e = 0; e < 4; e++) {
                int dd = dg * 4 + e;
                float4 qa = *(const float4*)&Qt[dd * 64 + qg];
                float4 ka = *(const float4*)&Kt[dd * 64 + kg];
                u64 k01 = pk2(ka.x, ka.y), k23 = pk2(ka.z, ka.w);
                float qv[4] = {qa.x, qa.y, qa.z, qa.w};
#pragma unroll
                for (int i = 0; i < 4; i++) {
                    u64 a2 = dup2(qv[i]);
                    S2[i][0] = fma2(a2, k01, S2[i][0]);
                    S2[i][1] = fma2(a2, k23, S2[i][1]);
                }
            }
        }

        float S[4][4];
#pragma unroll
        for (int i = 0; i < 4; i++) {
            float2 s01 = up2(S2[i][0]), s23 = up2(S2[i][1]);
            S[i][0] = s01.x; S[i][1] = s01.y; S[i][2] = s23.x; S[i][3] = s23.y;
        }

        // scale + pair bias (mask already folded into z)
#pragma unroll
        for (int i = 0; i < 4; i++) {
            float4 zv = *(const float4*)(g_z + (size_t)h * 1048576 +
                                         (size_t)(i0 + ty * 4 + i) * 1024 + j0 + (tx << 2));
            S[i][0] = S[i][0] * 0.125f + zv.x;
            S[i][1] = S[i][1] * 0.125f + zv.y;
            S[i][2] = S[i][2] * 0.125f + zv.z;
            S[i][3] = S[i][3] * 0.125f + zv.w;
        }

        // online softmax (row stats reduced across the 16 tx lanes)
#pragma unroll
        for (int i = 0; i < 4; i++) {
            float mx = fmaxf(fmaxf(S[i][0], S[i][1]), fmaxf(S[i][2], S[i][3]));
            mx = fmaxf(mx, __shfl_xor_sync(0xffffffffu, mx, 1));
            mx = fmaxf(mx, __shfl_xor_sync(0xffffffffu, mx, 2));
            mx = fmaxf(mx, __shfl_xor_sync(0xffffffffu, mx, 4));
            mx = fmaxf(mx, __shfl_xor_sync(0xffffffffu, mx, 8));
            float mnew = fmaxf(m[i], mx);
            float corr = __expf(m[i] - mnew);
            float rs = 0.f;
#pragma unroll
            for (int j = 0; j < 4; j++) {
                float p = __expf(S[i][j] - mnew);
                S[i][j] = p;
                rs += p;
            }
            rs += __shfl_xor_sync(0xffffffffu, rs, 1);
            rs += __shfl_xor_sync(0xffffffffu, rs, 2);
            rs += __shfl_xor_sync(0xffffffffu, rs, 4);
            rs += __shfl_xor_sync(0xffffffffu, rs, 8);
            l[i] = l[i] * corr + rs;
            m[i] = mnew;
            u64 c2 = dup2(corr);
            O2[i][0] = mul2(O2[i][0], c2);
            O2[i][1] = mul2(O2[i][1], c2);
        }

        // write P tile (natural layout, pad 68 -> broadcast-clean reads)
#pragma unroll
        for (int i = 0; i < 4; i++)
            *(float4*)&Ps[(ty * 4 + i) * 68 + (tx << 2)] =
                make_float4(S[i][0], S[i][1], S[i][2], S[i][3]);
        __syncthreads();

        // O += P V   (packed f32x2 over d)
#pragma unroll 8
        for (int jj = 0; jj < 64; jj++) {
            float4 va = *(const float4*)&Vs[jj * 64 + (tx << 2)];
            u64 v01 = pk2(va.x, va.y), v23 = pk2(va.z, va.w);
#pragma unroll
            for (int i = 0; i < 4; i++) {
                u64 p2 = dup2(Ps[(ty * 4 + i) * 68 + jj]);
                O2[i][0] = fma2(p2, v01, O2[i][0]);
                O2[i][1] = fma2(p2, v23, O2[i][1]);
            }
        }
    }

    // epilogue: normalize + fuse gating multiply
#pragma unroll
    for (int i = 0; i < 4; i++) {
        float inv = 1.f / l[i];
        size_t idx = (size_t)(i0 + ty * 4 + i) * CS + colbase + (tx << 2);
        float4 gg = *(const float4*)(g_g + idx);
        float2 o01 = up2(O2[i][0]), o23 = up2(O2[i][1]);
        float4 o;
        o.x = o01.x * inv * gg.x;
        o.y = o01.y * inv * gg.y;
        o.z = o23.x * inv * gg.z;
        o.w = o23.y * inv * gg.w;
        *(float4*)(g_tmp + idx) = o;
    }
}

// ---------------- launch ----------------------------------------------------
extern "C" void kernel_launch(void* const* d_in, const int* in_sizes, int n_in,
                              void* d_out, int out_size) {
    const float* s    = (const float*)d_in[0];
    const float* kin  = (const float*)d_in[1];
    const float* mask = (const float*)d_in[2];
    const float* bias = (const float*)d_in[3];
    const float* Wq   = (const float*)d_in[4];
    const float* bq   = (const float*)d_in[5];
    const float* Wk   = (const float*)d_in[6];
    const float* Wv   = (const float*)d_in[7];
    const float* Wg   = (const float*)d_in[8];
    const float* Wo   = (const float*)d_in[9];
    const float* Wz   = (const float*)d_in[10];
    // d_in[11] = multiplicity (must be 1 with B=1; repeat is a no-op)
    float* out = (float*)d_out;

    // 66560 B dynamic smem for attention (Qt+Kt+Vs 48KB + Ps 17408B).
    // Not a stream op -> graph-capture safe; idempotent per call.
    cudaFuncSetAttribute(attn_kernel, cudaFuncAttributeMaxDynamicSharedMemorySize, 66560);

    proj_kernel<<<dim3(8, 8, 4), 256>>>(s, kin, Wq, bq, Wk, Wv, Wg);
    z_kernel<<<16384, 64>>>(bias, Wz, mask);
    attn_kernel<<<dim3(16, 16), 256, 66560>>>();
    out_kernel<<<dim3(16, 8), 256>>>(Wo, out);
}

// round 5
// speedup vs baseline: 1.3309x; 1.3309x over previous
#include <cuda_runtime.h>
#include <cuda_bf16.h>
#include <cstdint>
#include <math.h>

#define CS 1024
#define NH 16
#define HD 64

typedef unsigned int u32;

// ---------------- scratch (static device globals; no runtime allocation) ----
__device__ float g_q[1024 * 1024];
__device__ float g_k[1024 * 1024];
__device__ float g_v[1024 * 1024];
__device__ float g_g[1024 * 1024];
__device__ float g_z[16 * 1024 * 1024];   // [h][i][j]

// bf16 hi/lo split operands for tensor-core GEMMs
__device__ __nv_bfloat16 g_s_hi[1024 * 1024],  g_s_lo[1024 * 1024];
__device__ __nv_bfloat16 g_ki_hi[1024 * 1024], g_ki_lo[1024 * 1024];
__device__ __nv_bfloat16 g_wq_hi[1024 * 1024], g_wq_lo[1024 * 1024];
__device__ __nv_bfloat16 g_wk_hi[1024 * 1024], g_wk_lo[1024 * 1024];
__device__ __nv_bfloat16 g_wv_hi[1024 * 1024], g_wv_lo[1024 * 1024];
__device__ __nv_bfloat16 g_wg_hi[1024 * 1024], g_wg_lo[1024 * 1024];
__device__ __nv_bfloat16 g_wo_hi[1024 * 1024], g_wo_lo[1024 * 1024];
__device__ __nv_bfloat16 g_ot_hi[1024 * 1024], g_ot_lo[1024 * 1024];

// ---------------- helpers ---------------------------------------------------
__device__ __forceinline__ u32 smem_u32(const void* p) {
    u32 a;
    asm("{ .reg .u64 t; cvta.to.shared.u64 t, %1; cvt.u32.u64 %0, t; }" : "=r"(a) : "l"(p));
    return a;
}
__device__ __forceinline__ void ldm_x4(u32 addr, u32* r) {
    asm volatile("ldmatrix.sync.aligned.m8n8.x4.shared.b16 {%0,%1,%2,%3}, [%4];"
                 : "=r"(r[0]), "=r"(r[1]), "=r"(r[2]), "=r"(r[3]) : "r"(addr));
}
__device__ __forceinline__ void mma16816(float* c, const u32* a, const u32* b) {
    asm volatile(
        "mma.sync.aligned.m16n8k16.row.col.f32.bf16.bf16.f32 "
        "{%0,%1,%2,%3},{%4,%5,%6,%7},{%8,%9},{%0,%1,%2,%3};"
        : "+f"(c[0]), "+f"(c[1]), "+f"(c[2]), "+f"(c[3])
        : "r"(a[0]), "r"(a[1]), "r"(a[2]), "r"(a[3]), "r"(b[0]), "r"(b[1]));
}
__device__ __forceinline__ u32 pkbf2(__nv_bfloat16 a, __nv_bfloat16 b) {
    __nv_bfloat162 t = __halves2bfloat162(a, b);
    return *(u32*)&t;
}

// ---------------- fp32 -> bf16 hi/lo split ----------------------------------
__global__ __launch_bounds__(256) void split_kernel(const float* __restrict__ s,
                                                    const float* __restrict__ kin,
                                                    const float* __restrict__ wq,
                                                    const float* __restrict__ wk,
                                                    const float* __restrict__ wv,
                                                    const float* __restrict__ wg,
                                                    const float* __restrict__ wo) {
    const float* src;
    __nv_bfloat16 *dh, *dl;
    switch (blockIdx.y) {
        case 0: src = s;   dh = g_s_hi;  dl = g_s_lo;  break;
        case 1: src = kin; dh = g_ki_hi; dl = g_ki_lo; break;
        case 2: src = wq;  dh = g_wq_hi; dl = g_wq_lo; break;
        case 3: src = wk;  dh = g_wk_hi; dl = g_wk_lo; break;
        case 4: src = wv;  dh = g_wv_hi; dl = g_wv_lo; break;
        case 5: src = wg;  dh = g_wg_hi; dl = g_wg_lo; break;
        default: src = wo; dh = g_wo_hi; dl = g_wo_lo; break;
    }
    size_t i = ((size_t)blockIdx.x * 256 + threadIdx.x) * 4;
    float4 v = *(const float4*)(src + i);
    __nv_bfloat16 h0 = __float2bfloat16(v.x), h1 = __float2bfloat16(v.y);
    __nv_bfloat16 h2 = __float2bfloat16(v.z), h3 = __float2bfloat16(v.w);
    __nv_bfloat16 l0 = __float2bfloat16(v.x - __bfloat162float(h0));
    __nv_bfloat16 l1 = __float2bfloat16(v.y - __bfloat162float(h1));
    __nv_bfloat16 l2 = __float2bfloat16(v.z - __bfloat162float(h2));
    __nv_bfloat16 l3 = __float2bfloat16(v.w - __bfloat162float(h3));
    *(uint2*)(dh + i) = make_uint2(pkbf2(h0, h1), pkbf2(h2, h3));
    *(uint2*)(dl + i) = make_uint2(pkbf2(l0, l1), pkbf2(l2, l3));
}

// ---------------- HMMA GEMM tile: C[128,128] = A * B^T (3-term bf16 split) --
// MODE 0: plain, 1: +bias[n], 2: sigmoid
template <int MODE>
__device__ __forceinline__ void hmma_tile(const __nv_bfloat16* __restrict__ Ah,
                                          const __nv_bfloat16* __restrict__ Al,
                                          const __nv_bfloat16* __restrict__ Bh,
                                          const __nv_bfloat16* __restrict__ Bl,
                                          float* __restrict__ C,
                                          const float* __restrict__ bias,
                                          int bm0, int bn0) {
    extern __shared__ char smem[];
    const int tid = threadIdx.x;
    const int lane = tid & 31, wid = tid >> 5;
    const int wm = wid & 1, wn = wid >> 1;          // 2 x 4 warp grid
    const u32 sbase = smem_u32(smem);

    float acc[4][4][4];
#pragma unroll
    for (int mt = 0; mt < 4; mt++)
#pragma unroll
        for (int nt = 0; nt < 4; nt++)
#pragma unroll
            for (int e = 0; e < 4; e++) acc[mt][nt][e] = 0.f;

    for (int kt = 0; kt < 16; kt++) {
        __syncthreads();
        // stage Ahi/Alo/Bhi/Blo: 128 rows x 64 bf16 (128B/row), SW128 swizzle
#pragma unroll
        for (int op = 0; op < 4; op++) {
            const __nv_bfloat16* src = (op == 0) ? Ah : (op == 1) ? Al : (op == 2) ? Bh : Bl;
            const int r0 = (op < 2) ? bm0 : bn0;
            char* dst = smem + op * 16384;
#pragma unroll
            for (int u = 0; u < 4; u++) {
                int lin = tid + u * 256;
                int row = lin >> 3;
                u32 off = (u32)(row * 128 + ((lin & 7) << 4));
                u32 sw = off ^ ((off >> 3) & 0x70);
                *(float4*)(dst + sw) =
                    *(const float4*)(src + (size_t)(r0 + row) * 1024 + kt * 64 + ((lin & 7) << 3));
            }
        }
        __syncthreads();

#pragma unroll
        for (int ks = 0; ks < 4; ks++) {
            u32 ah[4][4], al[4][4], bh[2][4], bl[2][4];
#pragma unroll
            for (int mt = 0; mt < 4; mt++) {
                int row = wm * 64 + mt * 16 + (lane & 15);
                int ch = ks * 2 + (lane >> 4);
                u32 addr = sbase + row * 128 + ((u32)(ch ^ (row & 7)) << 4);
                ldm_x4(addr, ah[mt]);
                ldm_x4(addr + 16384, al[mt]);
            }
#pragma unroll
            for (int nh = 0; nh < 2; nh++) {
                int row = wn * 32 + nh * 16 + (lane & 7) + ((lane >> 4) << 3);
                int ch = ks * 2 + ((lane >> 3) & 1);
                u32 addr = sbase + 32768 + row * 128 + ((u32)(ch ^ (row & 7)) << 4);
                ldm_x4(addr, bh[nh]);
                ldm_x4(addr + 16384, bl[nh]);
            }
#pragma unroll
            for (int mt = 0; mt < 4; mt++)
#pragma unroll
                for (int nt = 0; nt < 4; nt++) {
                    const u32* bhp = &bh[nt >> 1][(nt & 1) * 2];
                    const u32* blp = &bl[nt >> 1][(nt & 1) * 2];
                    mma16816(acc[mt][nt], ah[mt], bhp);
                    mma16816(acc[mt][nt], ah[mt], blp);
                    mma16816(acc[mt][nt], al[mt], bhp);
                }
        }
    }

    // epilogue: canonical m16n8 C fragment mapping, float2 stores
#pragma unroll
    for (int mt = 0; mt < 4; mt++) {
        int r0 = bm0 + wm * 64 + mt * 16 + (lane >> 2);
#pragma unroll
        for (int nt = 0; nt < 4; nt++) {
            int c0 = bn0 + wn * 32 + nt * 8 + (lane & 3) * 2;
            float v0 = acc[mt][nt][0], v1 = acc[mt][nt][1];
            float v2 = acc[mt][nt][2], v3 = acc[mt][nt][3];
            if (MODE == 1) {
                float b0 = bias[c0], b1 = bias[c0 + 1];
                v0 += b0; v1 += b1; v2 += b0; v3 += b1;
            }
            if (MODE == 2) {
                v0 = 1.f / (1.f + __expf(-v0)); v1 = 1.f / (1.f + __expf(-v1));
                v2 = 1.f / (1.f + __expf(-v2)); v3 = 1.f / (1.f + __expf(-v3));
            }
            *(float2*)(C + (size_t)r0 * 1024 + c0) = make_float2(v0, v1);
            *(float2*)(C + (size_t)(r0 + 8) * 1024 + c0) = make_float2(v2, v3);
        }
    }
}

// ---------------- fused projections q,k,v,g (HMMA) --------------------------
__global__ __launch_bounds__(256) void proj_tc_kernel(const float* __restrict__ bq) {
    const int bm0 = blockIdx.y * 128, bn0 = blockIdx.x * 128;
    switch (blockIdx.z) {
        case 0: hmma_tile<1>(g_s_hi, g_s_lo, g_wq_hi, g_wq_lo, g_q, bq, bm0, bn0); break;
        case 1: hmma_tile<0>(g_ki_hi, g_ki_lo, g_wk_hi, g_wk_lo, g_k, nullptr, bm0, bn0); break;
        case 2: hmma_tile<0>(g_ki_hi, g_ki_lo, g_wv_hi, g_wv_lo, g_v, nullptr, bm0, bn0); break;
        default: hmma_tile<2>(g_s_hi, g_s_lo, g_wg_hi, g_wg_lo, g_g, nullptr, bm0, bn0); break;
    }
}

// ---------------- output GEMM: out = (g*o) @ Wo^T (HMMA) --------------------
__global__ __launch_bounds__(256) void out_tc_kernel(float* __restrict__ out) {
    hmma_tile<0>(g_ot_hi, g_ot_lo, g_wo_hi, g_wo_lo, out, nullptr,
                 blockIdx.y * 128, blockIdx.x * 128);
}

// ---------------- pair-bias projection z[h][i][j] + mask --------------------
__global__ __launch_bounds__(64) void z_kernel(const float* __restrict__ bias,
                                               const float* __restrict__ Wz,
                                               const float* __restrict__ mask) {
    __shared__ float sb[64 * 132];
    __shared__ float swz[128 * 16];
    const int tid = threadIdx.x;
    const size_t p0 = (size_t)blockIdx.x * 64;

    for (int idx = tid; idx < 128 * 16; idx += 64) swz[idx] = Wz[idx];
#pragma unroll
    for (int u = 0; u < 32; u++) {
        int lin = tid + u * 64;
        int pr = lin >> 5;
        int pc = (lin & 31) << 2;
        float4 v = *(const float4*)(bias + ((p0 + pr) << 7) + pc);
        *(float4*)&sb[pr * 132 + pc] = v;
    }
    __syncthreads();

    const int hg = tid & 3;
    const int pg = tid >> 2;
    float acc[4][4];
#pragma unroll
    for (int i = 0; i < 4; i++)
#pragma unroll
        for (int q = 0; q < 4; q++) acc[i][q] = 0.f;

#pragma unroll 4
    for (int c = 0; c < 128; c++) {
        float w[4];
        *(float4*)w = *(const float4*)&swz[c * 16 + hg * 4];
#pragma unroll
        for (int i = 0; i < 4; i++) {
            float bv = sb[(pg + 16 * i) * 132 + c];
            acc[i][0] += bv * w[0];
            acc[i][1] += bv * w[1];
            acc[i][2] += bv * w[2];
            acc[i][3] += bv * w[3];
        }
    }

#pragma unroll
    for (int i = 0; i < 4; i++) {
        size_t pair = p0 + pg + 16 * i;
        int j = (int)(pair & 1023);
        float madd = (1.f - mask[j]) * (-1000000.f);
#pragma unroll
        for (int q = 0; q < 4; q++) {
            int hh = hg * 4 + q;
            g_z[(size_t)hh * 1048576 + pair] = acc[i][q] + madd;
        }
    }
}

// ---------------- flash attention + fused gating + bf16 split ---------------
__global__ __launch_bounds__(256) void attn_kernel() {
    extern __shared__ float sm[];
    float* Qt = sm;
    float* Kt = sm + 4096;
    float* Vs = sm + 8192;
    float* Ps = sm + 12288;

    const int tid = threadIdx.x;
    const int tx = tid & 15;
    const int ty = tid >> 4;
    const int h = blockIdx.y;
    const int i0 = blockIdx.x * 64;
    const int colbase = h * 64;

#pragma unroll
    for (int u = 0; u < 4; u++) {
        int lin = tid + u * 256;
        int r = lin >> 4;
        int d4 = lin & 15;
        float4 v = *(const float4*)(g_q + (size_t)(i0 + r) * CS + colbase + (d4 << 2));
        int grp = ((r >> 2) ^ d4) & 15;
        float* p = Qt + ((d4 << 2) << 6) + (grp << 2) + (r & 3);
        p[0] = v.x; p[64] = v.y; p[128] = v.z; p[192] = v.w;
    }

    float m[4], l[4], O[4][4];
#pragma unroll
    for (int i = 0; i < 4; i++) {
        m[i] = -1e30f; l[i] = 0.f;
#pragma unroll
        for (int j = 0; j < 4; j++) O[i][j] = 0.f;
    }

    for (int j0 = 0; j0 < 1024; j0 += 64) {
        __syncthreads();
#pragma unroll
        for (int u = 0; u < 4; u++) {
            int lin = tid + u * 256;
            int r = lin >> 4;
            int d4 = lin & 15;
            float4 kv = *(const float4*)(g_k + (size_t)(j0 + r) * CS + colbase + (d4 << 2));
            int grp = ((r >> 2) ^ d4) & 15;
            float* p = Kt + ((d4 << 2) << 6) + (grp << 2) + (r & 3);
            p[0] = kv.x; p[64] = kv.y; p[128] = kv.z; p[192] = kv.w;
            float4 vv = *(const float4*)(g_v + (size_t)(j0 + r) * CS + colbase + (d4 << 2));
            *(float4*)&Vs[r * 64 + (d4 << 2)] = vv;
        }
        __syncthreads();

        float S[4][4];
#pragma unroll
        for (int i = 0; i < 4; i++)
#pragma unroll
            for (int j = 0; j < 4; j++) S[i][j] = 0.f;

#pragma unroll 4
        for (int dg = 0; dg < 16; dg++) {
            const int qg = ((ty ^ dg) & 15) << 2;
            const int kg = ((tx ^ dg) & 15) << 2;
#pragma unroll
            for (int e = 0; e < 4; e++) {
                int dd = dg * 4 + e;
                float qa[4], ka[4];
                *(float4*)qa = *(const float4*)&Qt[dd * 64 + qg];
                *(float4*)ka = *(const float4*)&Kt[dd * 64 + kg];
#pragma unroll
                for (int i = 0; i < 4; i++)
#pragma unroll
                    for (int j = 0; j < 4; j++) S[i][j] += qa[i] * ka[j];
            }
        }

#pragma unroll
        for (int i = 0; i < 4; i++) {
            float4 zv = *(const float4*)(g_z + (size_t)h * 1048576 +
                                         (size_t)(i0 + ty * 4 + i) * 1024 + j0 + (tx << 2));
            S[i][0] = S[i][0] * 0.125f + zv.x;
            S[i][1] = S[i][1] * 0.125f + zv.y;
            S[i][2] = S[i][2] * 0.125f + zv.z;
            S[i][3] = S[i][3] * 0.125f + zv.w;
        }

#pragma unroll
        for (int i = 0; i < 4; i++) {
            float mx = fmaxf(fmaxf(S[i][0], S[i][1]), fmaxf(S[i][2], S[i][3]));
            mx = fmaxf(mx, __shfl_xor_sync(0xffffffffu, mx, 1));
            mx = fmaxf(mx, __shfl_xor_sync(0xffffffffu, mx, 2));
            mx = fmaxf(mx, __shfl_xor_sync(0xffffffffu, mx, 4));
            mx = fmaxf(mx, __shfl_xor_sync(0xffffffffu, mx, 8));
            float mnew = fmaxf(m[i], mx);
            float corr = __expf(m[i] - mnew);
            float rs = 0.f;
#pragma unroll
            for (int j = 0; j < 4; j++) {
                float p = __expf(S[i][j] - mnew);
                S[i][j] = p;
                rs += p;
            }
            rs += __shfl_xor_sync(0xffffffffu, rs, 1);
            rs += __shfl_xor_sync(0xffffffffu, rs, 2);
            rs += __shfl_xor_sync(0xffffffffu, rs, 4);
            rs += __shfl_xor_sync(0xffffffffu, rs, 8);
            l[i] = l[i] * corr + rs;
            m[i] = mnew;
#pragma unroll
            for (int j = 0; j < 4; j++) O[i][j] *= corr;
        }

#pragma unroll
        for (int i = 0; i < 4; i++)
            *(float4*)&Ps[(ty * 4 + i) * 68 + (tx << 2)] =
                make_float4(S[i][0], S[i][1], S[i][2], S[i][3]);
        __syncthreads();

#pragma unroll 8
        for (int jj = 0; jj < 64; jj++) {
            float va[4];
            *(float4*)va = *(const float4*)&Vs[jj * 64 + (tx << 2)];
#pragma unroll
            for (int i = 0; i < 4; i++) {
                float p = Ps[(ty * 4 + i) * 68 + jj];
                O[i][0] += p * va[0];
                O[i][1] += p * va[1];
                O[i][2] += p * va[2];
                O[i][3] += p * va[3];
            }
        }
    }

    // epilogue: normalize + gate + bf16 hi/lo split for the out GEMM
#pragma unroll
    for (int i = 0; i < 4; i++) {
        float inv = 1.f / l[i];
        size_t idx = (size_t)(i0 + ty * 4 + i) * CS + colbase + (tx << 2);
        float4 gg = *(const float4*)(g_g + idx);
        float o0 = O[i][0] * inv * gg.x;
        float o1 = O[i][1] * inv * gg.y;
        float o2 = O[i][2] * inv * gg.z;
        float o3 = O[i][3] * inv * gg.w;
        __nv_bfloat16 h0 = __float2bfloat16(o0), h1 = __float2bfloat16(o1);
        __nv_bfloat16 h2 = __float2bfloat16(o2), h3 = __float2bfloat16(o3);
        __nv_bfloat16 l0 = __float2bfloat16(o0 - __bfloat162float(h0));
        __nv_bfloat16 l1 = __float2bfloat16(o1 - __bfloat162float(h1));
        __nv_bfloat16 l2 = __float2bfloat16(o2 - __bfloat162float(h2));
        __nv_bfloat16 l3 = __float2bfloat16(o3 - __bfloat162float(h3));
        *(uint2*)(g_ot_hi + idx) = make_uint2(pkbf2(h0, h1), pkbf2(h2, h3));
        *(uint2*)(g_ot_lo + idx) = make_uint2(pkbf2(l0, l1), pkbf2(l2, l3));
    }
}

// ---------------- launch ----------------------------------------------------
extern "C" void kernel_launch(void* const* d_in, const int* in_sizes, int n_in,
                              void* d_out, int out_size) {
    const float* s    = (const float*)d_in[0];
    const float* kin  = (const float*)d_in[1];
    const float* mask = (const float*)d_in[2];
    const float* bias = (const float*)d_in[3];
    const float* Wq   = (const float*)d_in[4];
    const float* bq   = (const float*)d_in[5];
    const float* Wk   = (const float*)d_in[6];
    const float* Wv   = (const float*)d_in[7];
    const float* Wg   = (const float*)d_in[8];
    const float* Wo   = (const float*)d_in[9];
    const float* Wz   = (const float*)d_in[10];
    float* out = (float*)d_out;

    cudaFuncSetAttribute(proj_tc_kernel, cudaFuncAttributeMaxDynamicSharedMemorySize, 65536);
    cudaFuncSetAttribute(out_tc_kernel,  cudaFuncAttributeMaxDynamicSharedMemorySize, 65536);
    cudaFuncSetAttribute(attn_kernel,    cudaFuncAttributeMaxDynamicSharedMemorySize, 66560);

    split_kernel<<<dim3(1024, 7), 256>>>(s, kin, Wq, Wk, Wv, Wg, Wo);
    proj_tc_kernel<<<dim3(8, 8, 4), 256, 65536>>>(bq);
    z_kernel<<<16384, 64>>>(bias, Wz, mask);
    attn_kernel<<<dim3(16, 16), 256, 66560>>>();
    out_tc_kernel<<<dim3(8, 8), 256, 65536>>>(out);
}

// round 6
// speedup vs baseline: 1.5631x; 1.1744x over previous
#include <cuda_runtime.h>
#include <cuda_bf16.h>
#include <cstdint>
#include <math.h>

#define CS 1024
#define NH 16
#define HD 64

typedef unsigned int u32;

// ---------------- scratch (static device globals; no runtime allocation) ----
__device__ float g_g[1024 * 1024];
__device__ float g_z[16 * 1024 * 1024];   // [h][i][j]

// bf16 hi/lo split operands for tensor-core GEMMs
__device__ __nv_bfloat16 g_s_hi[1024 * 1024],  g_s_lo[1024 * 1024];
__device__ __nv_bfloat16 g_ki_hi[1024 * 1024], g_ki_lo[1024 * 1024];
__device__ __nv_bfloat16 g_wq_hi[1024 * 1024], g_wq_lo[1024 * 1024];
__device__ __nv_bfloat16 g_wk_hi[1024 * 1024], g_wk_lo[1024 * 1024];
__device__ __nv_bfloat16 g_wv_hi[1024 * 1024], g_wv_lo[1024 * 1024];
__device__ __nv_bfloat16 g_wg_hi[1024 * 1024], g_wg_lo[1024 * 1024];
__device__ __nv_bfloat16 g_wo_hi[1024 * 1024], g_wo_lo[1024 * 1024];
__device__ __nv_bfloat16 g_ot_hi[1024 * 1024], g_ot_lo[1024 * 1024];
// q,k,v stored directly as bf16 hi/lo from projection epilogue
__device__ __nv_bfloat16 g_qh[1024 * 1024], g_ql[1024 * 1024];
__device__ __nv_bfloat16 g_kh[1024 * 1024], g_kl[1024 * 1024];
__device__ __nv_bfloat16 g_vh[1024 * 1024], g_vl[1024 * 1024];

// ---------------- helpers ---------------------------------------------------
__device__ __forceinline__ u32 smem_u32(const void* p) {
    u32 a;
    asm("{ .reg .u64 t; cvta.to.shared.u64 t, %1; cvt.u32.u64 %0, t; }" : "=r"(a) : "l"(p));
    return a;
}
__device__ __forceinline__ void ldm_x4(u32 addr, u32* r) {
    asm volatile("ldmatrix.sync.aligned.m8n8.x4.shared.b16 {%0,%1,%2,%3}, [%4];"
                 : "=r"(r[0]), "=r"(r[1]), "=r"(r[2]), "=r"(r[3]) : "r"(addr));
}
__device__ __forceinline__ void ldm_x4_t(u32 addr, u32* r) {
    asm volatile("ldmatrix.sync.aligned.m8n8.x4.trans.shared.b16 {%0,%1,%2,%3}, [%4];"
                 : "=r"(r[0]), "=r"(r[1]), "=r"(r[2]), "=r"(r[3]) : "r"(addr));
}
__device__ __forceinline__ void mma16816(float* c, const u32* a, const u32* b) {
    asm volatile(
        "mma.sync.aligned.m16n8k16.row.col.f32.bf16.bf16.f32 "
        "{%0,%1,%2,%3},{%4,%5,%6,%7},{%8,%9},{%0,%1,%2,%3};"
        : "+f"(c[0]), "+f"(c[1]), "+f"(c[2]), "+f"(c[3])
        : "r"(a[0]), "r"(a[1]), "r"(a[2]), "r"(a[3]), "r"(b[0]), "r"(b[1]));
}
__device__ __forceinline__ u32 pkbf2(__nv_bfloat16 a, __nv_bfloat16 b) {
    __nv_bfloat162 t = __halves2bfloat162(a, b);
    return *(u32*)&t;
}
// pack the high 16 bits (truncated bf16) of two floats: low half = a
__device__ __forceinline__ u32 prmt_hi(float a, float b) {
    u32 r;
    asm("prmt.b32 %0, %1, %2, 0x7632;"
        : "=r"(r) : "r"(__float_as_uint(a)), "r"(__float_as_uint(b)));
    return r;
}
__device__ __forceinline__ float trunc_hi(float a) {
    return __uint_as_float(__float_as_uint(a) & 0xFFFF0000u);
}

// ---------------- fp32 -> bf16 hi/lo split ----------------------------------
__global__ __launch_bounds__(256) void split_kernel(const float* __restrict__ s,
                                                    const float* __restrict__ kin,
                                                    const float* __restrict__ wq,
                                                    const float* __restrict__ wk,
                                                    const float* __restrict__ wv,
                                                    const float* __restrict__ wg,
                                                    const float* __restrict__ wo) {
    const float* src;
    __nv_bfloat16 *dh, *dl;
    switch (blockIdx.y) {
        case 0: src = s;   dh = g_s_hi;  dl = g_s_lo;  break;
        case 1: src = kin; dh = g_ki_hi; dl = g_ki_lo; break;
        case 2: src = wq;  dh = g_wq_hi; dl = g_wq_lo; break;
        case 3: src = wk;  dh = g_wk_hi; dl = g_wk_lo; break;
        case 4: src = wv;  dh = g_wv_hi; dl = g_wv_lo; break;
        case 5: src = wg;  dh = g_wg_hi; dl = g_wg_lo; break;
        default: src = wo; dh = g_wo_hi; dl = g_wo_lo; break;
    }
    size_t i = ((size_t)blockIdx.x * 256 + threadIdx.x) * 4;
    float4 v = *(const float4*)(src + i);
    __nv_bfloat16 h0 = __float2bfloat16(v.x), h1 = __float2bfloat16(v.y);
    __nv_bfloat16 h2 = __float2bfloat16(v.z), h3 = __float2bfloat16(v.w);
    __nv_bfloat16 l0 = __float2bfloat16(v.x - __bfloat162float(h0));
    __nv_bfloat16 l1 = __float2bfloat16(v.y - __bfloat162float(h1));
    __nv_bfloat16 l2 = __float2bfloat16(v.z - __bfloat162float(h2));
    __nv_bfloat16 l3 = __float2bfloat16(v.w - __bfloat162float(h3));
    *(uint2*)(dh + i) = make_uint2(pkbf2(h0, h1), pkbf2(h2, h3));
    *(uint2*)(dl + i) = make_uint2(pkbf2(l0, l1), pkbf2(l2, l3));
}

// ---------------- HMMA GEMM tile: C[128,128] = A * B^T (3-term bf16 split) --
// MODE 0: fp32 store, 1: +bias then hi/lo split store, 2: sigmoid fp32 store,
// MODE 3: hi/lo split store
template <int MODE>
__device__ __forceinline__ void hmma_tile(const __nv_bfloat16* __restrict__ Ah,
                                          const __nv_bfloat16* __restrict__ Al,
                                          const __nv_bfloat16* __restrict__ Bh,
                                          const __nv_bfloat16* __restrict__ Bl,
                                          float* __restrict__ C,
                                          __nv_bfloat16* __restrict__ Ch,
                                          __nv_bfloat16* __restrict__ Cl,
                                          const float* __restrict__ bias,
                                          int bm0, int bn0) {
    extern __shared__ char smem[];
    const int tid = threadIdx.x;
    const int lane = tid & 31, wid = tid >> 5;
    const int wm = wid & 1, wn = wid >> 1;          // 2 x 4 warp grid
    const u32 sbase = smem_u32(smem);

    float acc[4][4][4];
#pragma unroll
    for (int mt = 0; mt < 4; mt++)
#pragma unroll
        for (int nt = 0; nt < 4; nt++)
#pragma unroll
            for (int e = 0; e < 4; e++) acc[mt][nt][e] = 0.f;

    for (int kt = 0; kt < 16; kt++) {
        __syncthreads();
#pragma unroll
        for (int op = 0; op < 4; op++) {
            const __nv_bfloat16* src = (op == 0) ? Ah : (op == 1) ? Al : (op == 2) ? Bh : Bl;
            const int r0 = (op < 2) ? bm0 : bn0;
            char* dst = smem + op * 16384;
#pragma unroll
            for (int u = 0; u < 4; u++) {
                int lin = tid + u * 256;
                int row = lin >> 3;
                u32 off = (u32)(row * 128 + ((lin & 7) << 4));
                u32 sw = off ^ ((off >> 3) & 0x70);
                *(float4*)(dst + sw) =
                    *(const float4*)(src + (size_t)(r0 + row) * 1024 + kt * 64 + ((lin & 7) << 3));
            }
        }
        __syncthreads();

#pragma unroll
        for (int ks = 0; ks < 4; ks++) {
            u32 ah[4][4], al[4][4], bh[2][4], bl[2][4];
#pragma unroll
            for (int mt = 0; mt < 4; mt++) {
                int row = wm * 64 + mt * 16 + (lane & 15);
                int ch = ks * 2 + (lane >> 4);
                u32 addr = sbase + row * 128 + ((u32)(ch ^ (row & 7)) << 4);
                ldm_x4(addr, ah[mt]);
                ldm_x4(addr + 16384, al[mt]);
            }
#pragma unroll
            for (int nh = 0; nh < 2; nh++) {
                int row = wn * 32 + nh * 16 + (lane & 7) + ((lane >> 4) << 3);
                int ch = ks * 2 + ((lane >> 3) & 1);
                u32 addr = sbase + 32768 + row * 128 + ((u32)(ch ^ (row & 7)) << 4);
                ldm_x4(addr, bh[nh]);
                ldm_x4(addr + 16384, bl[nh]);
            }
#pragma unroll
            for (int mt = 0; mt < 4; mt++)
#pragma unroll
                for (int nt = 0; nt < 4; nt++) {
                    const u32* bhp = &bh[nt >> 1][(nt & 1) * 2];
                    const u32* blp = &bl[nt >> 1][(nt & 1) * 2];
                    mma16816(acc[mt][nt], ah[mt], bhp);
                    mma16816(acc[mt][nt], ah[mt], blp);
                    mma16816(acc[mt][nt], al[mt], bhp);
                }
        }
    }

#pragma unroll
    for (int mt = 0; mt < 4; mt++) {
        int r0 = bm0 + wm * 64 + mt * 16 + (lane >> 2);
#pragma unroll
        for (int nt = 0; nt < 4; nt++) {
            int c0 = bn0 + wn * 32 + nt * 8 + (lane & 3) * 2;
            float v0 = acc[mt][nt][0], v1 = acc[mt][nt][1];
            float v2 = acc[mt][nt][2], v3 = acc[mt][nt][3];
            if (MODE == 1) {
                float b0 = bias[c0], b1 = bias[c0 + 1];
                v0 += b0; v1 += b1; v2 += b0; v3 += b1;
            }
            if (MODE == 2) {
                v0 = 1.f / (1.f + __expf(-v0)); v1 = 1.f / (1.f + __expf(-v1));
                v2 = 1.f / (1.f + __expf(-v2)); v3 = 1.f / (1.f + __expf(-v3));
            }
            if (MODE == 0 || MODE == 2) {
                *(float2*)(C + (size_t)r0 * 1024 + c0) = make_float2(v0, v1);
                *(float2*)(C + (size_t)(r0 + 8) * 1024 + c0) = make_float2(v2, v3);
            } else {
                *(u32*)(Ch + (size_t)r0 * 1024 + c0) = prmt_hi(v0, v1);
                *(u32*)(Ch + (size_t)(r0 + 8) * 1024 + c0) = prmt_hi(v2, v3);
                *(u32*)(Cl + (size_t)r0 * 1024 + c0) =
                    pkbf2(__float2bfloat16(v0 - trunc_hi(v0)), __float2bfloat16(v1 - trunc_hi(v1)));
                *(u32*)(Cl + (size_t)(r0 + 8) * 1024 + c0) =
                    pkbf2(__float2bfloat16(v2 - trunc_hi(v2)), __float2bfloat16(v3 - trunc_hi(v3)));
            }
        }
    }
}

// ---------------- fused projections q,k,v,g (HMMA) --------------------------
__global__ __launch_bounds__(256) void proj_tc_kernel(const float* __restrict__ bq) {
    const int bm0 = blockIdx.y * 128, bn0 = blockIdx.x * 128;
    switch (blockIdx.z) {
        case 0: hmma_tile<1>(g_s_hi, g_s_lo, g_wq_hi, g_wq_lo, nullptr, g_qh, g_ql, bq, bm0, bn0); break;
        case 1: hmma_tile<3>(g_ki_hi, g_ki_lo, g_wk_hi, g_wk_lo, nullptr, g_kh, g_kl, nullptr, bm0, bn0); break;
        case 2: hmma_tile<3>(g_ki_hi, g_ki_lo, g_wv_hi, g_wv_lo, nullptr, g_vh, g_vl, nullptr, bm0, bn0); break;
        default: hmma_tile<2>(g_s_hi, g_s_lo, g_wg_hi, g_wg_lo, g_g, nullptr, nullptr, nullptr, bm0, bn0); break;
    }
}

// ---------------- output GEMM: out = (g*o) @ Wo^T (HMMA) --------------------
__global__ __launch_bounds__(256) void out_tc_kernel(float* __restrict__ out) {
    hmma_tile<0>(g_ot_hi, g_ot_lo, g_wo_hi, g_wo_lo, out, nullptr, nullptr, nullptr,
                 blockIdx.y * 128, blockIdx.x * 128);
}

// ---------------- pair-bias projection z[h][i][j] + mask --------------------
__global__ __launch_bounds__(64) void z_kernel(const float* __restrict__ bias,
                                               const float* __restrict__ Wz,
                                               const float* __restrict__ mask) {
    __shared__ float sb[64 * 132];
    __shared__ float swz[128 * 16];
    const int tid = threadIdx.x;
    const size_t p0 = (size_t)blockIdx.x * 64;

    for (int idx = tid; idx < 128 * 16; idx += 64) swz[idx] = Wz[idx];
#pragma unroll
    for (int u = 0; u < 32; u++) {
        int lin = tid + u * 64;
        int pr = lin >> 5;
        int pc = (lin & 31) << 2;
        float4 v = *(const float4*)(bias + ((p0 + pr) << 7) + pc);
        *(float4*)&sb[pr * 132 + pc] = v;
    }
    __syncthreads();

    const int hg = tid & 3;
    const int pg = tid >> 2;
    float acc[4][4];
#pragma unroll
    for (int i = 0; i < 4; i++)
#pragma unroll
        for (int q = 0; q < 4; q++) acc[i][q] = 0.f;

#pragma unroll 4
    for (int c = 0; c < 128; c++) {
        float w[4];
        *(float4*)w = *(const float4*)&swz[c * 16 + hg * 4];
#pragma unroll
        for (int i = 0; i < 4; i++) {
            float bv = sb[(pg + 16 * i) * 132 + c];
            acc[i][0] += bv * w[0];
            acc[i][1] += bv * w[1];
            acc[i][2] += bv * w[2];
            acc[i][3] += bv * w[3];
        }
    }

#pragma unroll
    for (int i = 0; i < 4; i++) {
        size_t pair = p0 + pg + 16 * i;
        int j = (int)(pair & 1023);
        float madd = (1.f - mask[j]) * (-1000000.f);
#pragma unroll
        for (int q = 0; q < 4; q++) {
            int hh = hg * 4 + q;
            g_z[(size_t)hh * 1048576 + pair] = acc[i][q] + madd;
        }
    }
}

// ---------------- HMMA flash attention + fused gating -----------------------
// grid (8 i-blocks, 16 heads), 256 threads (8 warps x 16 query rows).
// smem: Qh 0..16K, Ql 16K..32K, Kh 32K..40K, Kl 40K..48K, Vh 48K..56K, Vl 56K..64K
__global__ __launch_bounds__(256) void attn_kernel() {
    extern __shared__ char smc[];
    const int tid = threadIdx.x, lane = tid & 31, w = tid >> 5;
    const int h = blockIdx.y;
    const int i0 = blockIdx.x * 128;
    const u32 sb = smem_u32(smc);
    const u32 Qhs = sb, Khs = sb + 32768, Vhs = sb + 49152;

    // stage Q hi/lo: 128 rows x 8 chunks of 16B each
#pragma unroll
    for (int u = 0; u < 4; u++) {
        int lin = tid + u * 256;
        int row = lin >> 3, ch = lin & 7;
        u32 sw16 = ((u32)(ch ^ (row & 7))) << 4;
        size_t go = (size_t)(i0 + row) * 2048 + h * 128 + (ch << 4);
        *(uint4*)(smc + row * 128 + sw16) = *(const uint4*)((const char*)g_qh + go);
        *(uint4*)(smc + 16384 + row * 128 + sw16) = *(const uint4*)((const char*)g_ql + go);
    }
    __syncthreads();

    // persistent Q fragments (warp rows w*16..w*16+15)
    u32 qh[4][4], ql[4][4];
    {
        int row = w * 16 + ((lane >> 3) & 1) * 8 + (lane & 7);
        u32 rbase = Qhs + row * 128;
#pragma unroll
        for (int kc = 0; kc < 4; kc++) {
            int ch = kc * 2 + (lane >> 4);
            u32 a = rbase + ((u32)(ch ^ (row & 7)) << 4);
            ldm_x4(a, qh[kc]);
            ldm_x4(a + 16384, ql[kc]);
        }
    }

    float m0 = -1e30f, m1 = -1e30f, l0 = 0.f, l1 = 0.f;
    float O[8][4];
#pragma unroll
    for (int nt = 0; nt < 8; nt++)
#pragma unroll
        for (int e = 0; e < 4; e++) O[nt][e] = 0.f;

    const float* zbase = g_z + (size_t)h * 1048576 +
                         (size_t)(i0 + w * 16 + (lane >> 2)) * 1024 + 2 * (lane & 3);

    for (int jt = 0; jt < 16; jt++) {
        const int j0g = jt * 64;
        __syncthreads();
        // stage K,V hi/lo tiles: 64 rows x 8 chunks each
#pragma unroll
        for (int u = 0; u < 2; u++) {
            int lin = tid + u * 256;
            int row = lin >> 3, ch = lin & 7;
            u32 sw16 = ((u32)(ch ^ (row & 7))) << 4;
            u32 so = row * 128 + sw16;
            size_t go = (size_t)(j0g + row) * 2048 + h * 128 + (ch << 4);
            *(uint4*)(smc + 32768 + so) = *(const uint4*)((const char*)g_kh + go);
            *(uint4*)(smc + 40960 + so) = *(const uint4*)((const char*)g_kl + go);
            *(uint4*)(smc + 49152 + so) = *(const uint4*)((const char*)g_vh + go);
            *(uint4*)(smc + 57344 + so) = *(const uint4*)((const char*)g_vl + go);
        }
        __syncthreads();

        // ---- S = Q K^T (16 x 64 per warp) ----
        float acc[8][4];
#pragma unroll
        for (int nt = 0; nt < 8; nt++)
#pragma unroll
            for (int e = 0; e < 4; e++) acc[nt][e] = 0.f;

#pragma unroll
        for (int kc = 0; kc < 4; kc++) {
            u32 kbh[4][4], kbl[4][4];
#pragma unroll
            for (int jp = 0; jp < 4; jp++) {
                int row = jp * 16 + (lane >> 4) * 8 + (lane & 7);
                int ch = kc * 2 + ((lane >> 3) & 1);
                u32 a = Khs + row * 128 + ((u32)(ch ^ (row & 7)) << 4);
                ldm_x4(a, kbh[jp]);
                ldm_x4(a + 8192, kbl[jp]);
            }
#pragma unroll
            for (int jp = 0; jp < 4; jp++)
#pragma unroll
                for (int hh = 0; hh < 2; hh++) {
                    int nt = jp * 2 + hh;
                    mma16816(acc[nt], qh[kc], &kbh[jp][hh * 2]);
                    mma16816(acc[nt], qh[kc], &kbl[jp][hh * 2]);
                    mma16816(acc[nt], ql[kc], &kbh[jp][hh * 2]);
                }
        }

        // ---- scale + z bias, online softmax ----
        const float* z0 = zbase + j0g;
        const float* z1 = z0 + 8192;     // +8 rows
        float mx0 = -1e30f, mx1 = -1e30f;
#pragma unroll
        for (int nt = 0; nt < 8; nt++) {
            float2 za = *(const float2*)(z0 + nt * 8);
            float2 zb = *(const float2*)(z1 + nt * 8);
            acc[nt][0] = acc[nt][0] * 0.125f + za.x;
            acc[nt][1] = acc[nt][1] * 0.125f + za.y;
            acc[nt][2] = acc[nt][2] * 0.125f + zb.x;
            acc[nt][3] = acc[nt][3] * 0.125f + zb.y;
            mx0 = fmaxf(mx0, fmaxf(acc[nt][0], acc[nt][1]));
            mx1 = fmaxf(mx1, fmaxf(acc[nt][2], acc[nt][3]));
        }
        mx0 = fmaxf(mx0, __shfl_xor_sync(0xffffffffu, mx0, 1));
        mx0 = fmaxf(mx0, __shfl_xor_sync(0xffffffffu, mx0, 2));
        mx1 = fmaxf(mx1, __shfl_xor_sync(0xffffffffu, mx1, 1));
        mx1 = fmaxf(mx1, __shfl_xor_sync(0xffffffffu, mx1, 2));
        float mn0 = fmaxf(m0, mx0), mn1 = fmaxf(m1, mx1);
        float cr0 = __expf(m0 - mn0), cr1 = __expf(m1 - mn1);
        float rs0 = 0.f, rs1 = 0.f;
#pragma unroll
        for (int nt = 0; nt < 8; nt++) {
            acc[nt][0] = __expf(acc[nt][0] - mn0);
            acc[nt][1] = __expf(acc[nt][1] - mn0);
            acc[nt][2] = __expf(acc[nt][2] - mn1);
            acc[nt][3] = __expf(acc[nt][3] - mn1);
            rs0 += acc[nt][0] + acc[nt][1];
            rs1 += acc[nt][2] + acc[nt][3];
        }
        rs0 += __shfl_xor_sync(0xffffffffu, rs0, 1);
        rs0 += __shfl_xor_sync(0xffffffffu, rs0, 2);
        rs1 += __shfl_xor_sync(0xffffffffu, rs1, 1);
        rs1 += __shfl_xor_sync(0xffffffffu, rs1, 2);
        l0 = l0 * cr0 + rs0; m0 = mn0;
        l1 = l1 * cr1 + rs1; m1 = mn1;
#pragma unroll
        for (int nt = 0; nt < 8; nt++) {
            O[nt][0] *= cr0; O[nt][1] *= cr0;
            O[nt][2] *= cr1; O[nt][3] *= cr1;
        }

        // ---- O += P V ----
#pragma unroll
        for (int kc = 0; kc < 4; kc++) {
            // P A-fragment from S tiles 2kc, 2kc+1 (hi trunc + exact residual lo)
            u32 pah[4], pal[4];
            {
                float* pa = acc[kc * 2];
                float* pb = acc[kc * 2 + 1];
                pah[0] = prmt_hi(pa[0], pa[1]);
                pah[1] = prmt_hi(pa[2], pa[3]);
                pah[2] = prmt_hi(pb[0], pb[1]);
                pah[3] = prmt_hi(pb[2], pb[3]);
                pal[0] = prmt_hi(pa[0] - trunc_hi(pa[0]), pa[1] - trunc_hi(pa[1]));
                pal[1] = prmt_hi(pa[2] - trunc_hi(pa[2]), pa[3] - trunc_hi(pa[3]));
                pal[2] = prmt_hi(pb[0] - trunc_hi(pb[0]), pb[1] - trunc_hi(pb[1]));
                pal[3] = prmt_hi(pb[2] - trunc_hi(pb[2]), pb[3] - trunc_hi(pb[3]));
            }
            u32 vbh[4][4], vbl[4][4];
#pragma unroll
            for (int dp = 0; dp < 4; dp++) {
                int row = kc * 16 + ((lane >> 3) & 1) * 8 + (lane & 7);
                int ch = dp * 2 + (lane >> 4);
                u32 a = Vhs + row * 128 + ((u32)(ch ^ (row & 7)) << 4);
                ldm_x4_t(a, vbh[dp]);
                ldm_x4_t(a + 8192, vbl[dp]);
            }
#pragma unroll
            for (int dp = 0; dp < 4; dp++)
#pragma unroll
                for (int hh = 0; hh < 2; hh++) {
                    int nt = dp * 2 + hh;
                    mma16816(O[nt], pah, &vbh[dp][hh * 2]);
                    mma16816(O[nt], pal, &vbh[dp][hh * 2]);
                    mma16816(O[nt], pah, &vbl[dp][hh * 2]);
                }
        }
    }

    // ---- epilogue: normalize + gate + bf16 hi/lo split ----
    l0 += __shfl_xor_sync(0xffffffffu, l0, 1);
    l0 += __shfl_xor_sync(0xffffffffu, l0, 2);
    l1 += __shfl_xor_sync(0xffffffffu, l1, 1);
    l1 += __shfl_xor_sync(0xffffffffu, l1, 2);
    // NOTE: l was summed per-thread then reduced; each lane in the quad summed
    // distinct columns, so the reduced value is the true row sum... but it was
    // already reduced per-tile above (rs shfl). Avoid double count: rs was
    // reduced each iteration, so l is already the full row sum — the two shfl
    // adds above would quadruple it uniformly across the quad. Compensate:
    l0 *= 0.25f; l1 *= 0.25f;
    float inv0 = 1.f / l0, inv1 = 1.f / l1;
    const int rg0 = i0 + w * 16 + (lane >> 2);
    const int cb = h * 64 + 2 * (lane & 3);
#pragma unroll
    for (int nt = 0; nt < 8; nt++) {
        int c = cb + nt * 8;
        float2 ga = *(const float2*)(g_g + (size_t)rg0 * 1024 + c);
        float2 gb = *(const float2*)(g_g + (size_t)(rg0 + 8) * 1024 + c);
        float o0 = O[nt][0] * inv0 * ga.x;
        float o1 = O[nt][1] * inv0 * ga.y;
        float o2 = O[nt][2] * inv1 * gb.x;
        float o3 = O[nt][3] * inv1 * gb.y;
        *(u32*)(g_ot_hi + (size_t)rg0 * 1024 + c) = prmt_hi(o0, o1);
        *(u32*)(g_ot_hi + (size_t)(rg0 + 8) * 1024 + c) = prmt_hi(o2, o3);
        *(u32*)(g_ot_lo + (size_t)rg0 * 1024 + c) =
            pkbf2(__float2bfloat16(o0 - trunc_hi(o0)), __float2bfloat16(o1 - trunc_hi(o1)));
        *(u32*)(g_ot_lo + (size_t)(rg0 + 8) * 1024 + c) =
            pkbf2(__float2bfloat16(o2 - trunc_hi(o2)), __float2bfloat16(o3 - trunc_hi(o3)));
    }
}

// ---------------- launch ----------------------------------------------------
extern "C" void kernel_launch(void* const* d_in, const int* in_sizes, int n_in,
                              void* d_out, int out_size) {
    const float* s    = (const float*)d_in[0];
    const float* kin  = (const float*)d_in[1];
    const float* mask = (const float*)d_in[2];
    const float* bias = (const float*)d_in[3];
    const float* Wq   = (const float*)d_in[4];
    const float* bq   = (const float*)d_in[5];
    const float* Wk   = (const float*)d_in[6];
    const float* Wv   = (const float*)d_in[7];
    const float* Wg   = (const float*)d_in[8];
    const float* Wo   = (const float*)d_in[9];
    const float* Wz   = (const float*)d_in[10];
    float* out = (float*)d_out;

    cudaFuncSetAttribute(proj_tc_kernel, cudaFuncAttributeMaxDynamicSharedMemorySize, 65536);
    cudaFuncSetAttribute(out_tc_kernel,  cudaFuncAttributeMaxDynamicSharedMemorySize, 65536);
    cudaFuncSetAttribute(attn_kernel,    cudaFuncAttributeMaxDynamicSharedMemorySize, 65536);

    split_kernel<<<dim3(1024, 7), 256>>>(s, kin, Wq, Wk, Wv, Wg, Wo);
    proj_tc_kernel<<<dim3(8, 8, 4), 256, 65536>>>(bq);
    z_kernel<<<16384, 64>>>(bias, Wz, mask);
    attn_kernel<<<dim3(8, 16), 256, 65536>>>();
    out_tc_kernel<<<dim3(8, 8), 256, 65536>>>(out);
}

// round 7
// speedup vs baseline: 1.7728x; 1.1342x over previous
#include <cuda_runtime.h>
#include <cuda_bf16.h>
#include <cstdint>
#include <math.h>

#define CS 1024
#define NH 16
#define HD 64

typedef unsigned int u32;

// ---------------- scratch (static device globals; no runtime allocation) ----
__device__ float g_g[1024 * 1024];
__device__ float g_z[16 * 1024 * 1024];   // [h][i][j]
__device__ float g_part[2][1024 * 1024];  // split-K partials for out GEMM

// bf16 hi/lo split operands for tensor-core GEMMs
__device__ __nv_bfloat16 g_s_hi[1024 * 1024],  g_s_lo[1024 * 1024];
__device__ __nv_bfloat16 g_ki_hi[1024 * 1024], g_ki_lo[1024 * 1024];
__device__ __nv_bfloat16 g_wq_hi[1024 * 1024], g_wq_lo[1024 * 1024];
__device__ __nv_bfloat16 g_wk_hi[1024 * 1024], g_wk_lo[1024 * 1024];
__device__ __nv_bfloat16 g_wv_hi[1024 * 1024], g_wv_lo[1024 * 1024];
__device__ __nv_bfloat16 g_wg_hi[1024 * 1024], g_wg_lo[1024 * 1024];
__device__ __nv_bfloat16 g_wo_hi[1024 * 1024], g_wo_lo[1024 * 1024];
__device__ __nv_bfloat16 g_ot_hi[1024 * 1024], g_ot_lo[1024 * 1024];
// q,k,v stored directly as bf16 hi/lo from projection epilogue
__device__ __nv_bfloat16 g_qh[1024 * 1024], g_ql[1024 * 1024];
__device__ __nv_bfloat16 g_kh[1024 * 1024], g_kl[1024 * 1024];
__device__ __nv_bfloat16 g_vh[1024 * 1024], g_vl[1024 * 1024];

// ---------------- helpers ---------------------------------------------------
__device__ __forceinline__ u32 smem_u32(const void* p) {
    u32 a;
    asm("{ .reg .u64 t; cvta.to.shared.u64 t, %1; cvt.u32.u64 %0, t; }" : "=r"(a) : "l"(p));
    return a;
}
__device__ __forceinline__ void ldm_x4(u32 addr, u32* r) {
    asm volatile("ldmatrix.sync.aligned.m8n8.x4.shared.b16 {%0,%1,%2,%3}, [%4];"
                 : "=r"(r[0]), "=r"(r[1]), "=r"(r[2]), "=r"(r[3]) : "r"(addr));
}
__device__ __forceinline__ void ldm_x4_t(u32 addr, u32* r) {
    asm volatile("ldmatrix.sync.aligned.m8n8.x4.trans.shared.b16 {%0,%1,%2,%3}, [%4];"
                 : "=r"(r[0]), "=r"(r[1]), "=r"(r[2]), "=r"(r[3]) : "r"(addr));
}
__device__ __forceinline__ void mma16816(float* c, const u32* a, const u32* b) {
    asm volatile(
        "mma.sync.aligned.m16n8k16.row.col.f32.bf16.bf16.f32 "
        "{%0,%1,%2,%3},{%4,%5,%6,%7},{%8,%9},{%0,%1,%2,%3};"
        : "+f"(c[0]), "+f"(c[1]), "+f"(c[2]), "+f"(c[3])
        : "r"(a[0]), "r"(a[1]), "r"(a[2]), "r"(a[3]), "r"(b[0]), "r"(b[1]));
}
__device__ __forceinline__ u32 pkbf2(__nv_bfloat16 a, __nv_bfloat16 b) {
    __nv_bfloat162 t = __halves2bfloat162(a, b);
    return *(u32*)&t;
}
__device__ __forceinline__ u32 prmt_hi(float a, float b) {
    u32 r;
    asm("prmt.b32 %0, %1, %2, 0x7632;"
        : "=r"(r) : "r"(__float_as_uint(a)), "r"(__float_as_uint(b)));
    return r;
}
__device__ __forceinline__ float trunc_hi(float a) {
    return __uint_as_float(__float_as_uint(a) & 0xFFFF0000u);
}
__device__ __forceinline__ void cpa16(u32 dst, const void* src) {
    asm volatile("cp.async.cg.shared.global [%0], [%1], 16;" :: "r"(dst), "l"(src));
}
#define CPA_COMMIT() asm volatile("cp.async.commit_group;" ::: "memory")
#define CPA_WAIT(n)  asm volatile("cp.async.wait_group %0;" :: "n"(n) : "memory")

// ---------------- fp32 -> bf16 hi/lo split ----------------------------------
__global__ __launch_bounds__(256) void split_kernel(const float* __restrict__ s,
                                                    const float* __restrict__ kin,
                                                    const float* __restrict__ wq,
                                                    const float* __restrict__ wk,
                                                    const float* __restrict__ wv,
                                                    const float* __restrict__ wg,
                                                    const float* __restrict__ wo) {
    const float* src;
    __nv_bfloat16 *dh, *dl;
    switch (blockIdx.y) {
        case 0: src = s;   dh = g_s_hi;  dl = g_s_lo;  break;
        case 1: src = kin; dh = g_ki_hi; dl = g_ki_lo; break;
        case 2: src = wq;  dh = g_wq_hi; dl = g_wq_lo; break;
        case 3: src = wk;  dh = g_wk_hi; dl = g_wk_lo; break;
        case 4: src = wv;  dh = g_wv_hi; dl = g_wv_lo; break;
        case 5: src = wg;  dh = g_wg_hi; dl = g_wg_lo; break;
        default: src = wo; dh = g_wo_hi; dl = g_wo_lo; break;
    }
    size_t i = ((size_t)blockIdx.x * 256 + threadIdx.x) * 4;
    float4 v = *(const float4*)(src + i);
    __nv_bfloat16 h0 = __float2bfloat16(v.x), h1 = __float2bfloat16(v.y);
    __nv_bfloat16 h2 = __float2bfloat16(v.z), h3 = __float2bfloat16(v.w);
    __nv_bfloat16 l0 = __float2bfloat16(v.x - __bfloat162float(h0));
    __nv_bfloat16 l1 = __float2bfloat16(v.y - __bfloat162float(h1));
    __nv_bfloat16 l2 = __float2bfloat16(v.z - __bfloat162float(h2));
    __nv_bfloat16 l3 = __float2bfloat16(v.w - __bfloat162float(h3));
    *(uint2*)(dh + i) = make_uint2(pkbf2(h0, h1), pkbf2(h2, h3));
    *(uint2*)(dl + i) = make_uint2(pkbf2(l0, l1), pkbf2(l2, l3));
}

// ---------------- pipelined HMMA GEMM tile: C[128,128] = A * B^T ------------
// 2-stage cp.async double buffer; 3-term bf16 split, term-ordered MMAs.
// MODE 0: fp32 store, 1: +bias then hi/lo split store, 2: sigmoid fp32 store,
// MODE 3: hi/lo split store
__device__ __forceinline__ void gemm_stage_ld(char* smem, int stage,
                                              const __nv_bfloat16* Ah,
                                              const __nv_bfloat16* Al,
                                              const __nv_bfloat16* Bh,
                                              const __nv_bfloat16* Bl,
                                              int bm0, int bn0, int kt, int tid) {
    const u32 sb = smem_u32(smem) + stage * 65536;
#pragma unroll
    for (int op = 0; op < 4; op++) {
        const __nv_bfloat16* src = (op == 0) ? Ah : (op == 1) ? Al : (op == 2) ? Bh : Bl;
        const int r0 = (op < 2) ? bm0 : bn0;
        const u32 d0 = sb + op * 16384;
#pragma unroll
        for (int u = 0; u < 4; u++) {
            int lin = tid + u * 256;
            int row = lin >> 3, ch = lin & 7;
            u32 sw = (u32)(row * 128) + ((u32)(ch ^ (row & 7)) << 4);
            cpa16(d0 + sw, src + (size_t)(r0 + row) * 1024 + kt * 64 + (ch << 3));
        }
    }
}

template <int MODE>
__device__ __forceinline__ void hmma_tile(const __nv_bfloat16* __restrict__ Ah,
                                          const __nv_bfloat16* __restrict__ Al,
                                          const __nv_bfloat16* __restrict__ Bh,
                                          const __nv_bfloat16* __restrict__ Bl,
                                          float* __restrict__ C,
                                          __nv_bfloat16* __restrict__ Ch,
                                          __nv_bfloat16* __restrict__ Cl,
                                          const float* __restrict__ bias,
                                          int bm0, int bn0, int kt0, int ktn) {
    extern __shared__ char smem[];
    const int tid = threadIdx.x;
    const int lane = tid & 31, wid = tid >> 5;
    const int wm = wid & 1, wn = wid >> 1;          // 2 x 4 warp grid
    const u32 sbase = smem_u32(smem);

    float acc[4][4][4];
#pragma unroll
    for (int mt = 0; mt < 4; mt++)
#pragma unroll
        for (int nt = 0; nt < 4; nt++)
#pragma unroll
            for (int e = 0; e < 4; e++) acc[mt][nt][e] = 0.f;

    gemm_stage_ld(smem, 0, Ah, Al, Bh, Bl, bm0, bn0, kt0, tid);
    CPA_COMMIT();

    for (int i = 0; i < ktn; i++) {
        if (i + 1 < ktn) {
            gemm_stage_ld(smem, (i + 1) & 1, Ah, Al, Bh, Bl, bm0, bn0, kt0 + i + 1, tid);
            CPA_COMMIT();
            CPA_WAIT(1);
        } else {
            CPA_WAIT(0);
        }
        __syncthreads();
        const u32 st = sbase + (u32)(i & 1) * 65536;

#pragma unroll
        for (int ks = 0; ks < 4; ks++) {
            u32 ah[4][4], al[4][4], bh[2][4], bl[2][4];
#pragma unroll
            for (int mt = 0; mt < 4; mt++) {
                int row = wm * 64 + mt * 16 + (lane & 15);
                int ch = ks * 2 + (lane >> 4);
                u32 addr = st + row * 128 + ((u32)(ch ^ (row & 7)) << 4);
                ldm_x4(addr, ah[mt]);
                ldm_x4(addr + 16384, al[mt]);
            }
#pragma unroll
            for (int nh = 0; nh < 2; nh++) {
                int row = wn * 32 + nh * 16 + (lane & 7) + ((lane >> 4) << 3);
                int ch = ks * 2 + ((lane >> 3) & 1);
                u32 addr = st + 32768 + row * 128 + ((u32)(ch ^ (row & 7)) << 4);
                ldm_x4(addr, bh[nh]);
                ldm_x4(addr + 16384, bl[nh]);
            }
            // term-ordered: each accumulator touched once per 16-MMA pass
#pragma unroll
            for (int mt = 0; mt < 4; mt++)
#pragma unroll
                for (int nt = 0; nt < 4; nt++)
                    mma16816(acc[mt][nt], ah[mt], &bh[nt >> 1][(nt & 1) * 2]);
#pragma unroll
            for (int mt = 0; mt < 4; mt++)
#pragma unroll
                for (int nt = 0; nt < 4; nt++)
                    mma16816(acc[mt][nt], ah[mt], &bl[nt >> 1][(nt & 1) * 2]);
#pragma unroll
            for (int mt = 0; mt < 4; mt++)
#pragma unroll
                for (int nt = 0; nt < 4; nt++)
                    mma16816(acc[mt][nt], al[mt], &bh[nt >> 1][(nt & 1) * 2]);
        }
        __syncthreads();
    }

#pragma unroll
    for (int mt = 0; mt < 4; mt++) {
        int r0 = bm0 + wm * 64 + mt * 16 + (lane >> 2);
#pragma unroll
        for (int nt = 0; nt < 4; nt++) {
            int c0 = bn0 + wn * 32 + nt * 8 + (lane & 3) * 2;
            float v0 = acc[mt][nt][0], v1 = acc[mt][nt][1];
            float v2 = acc[mt][nt][2], v3 = acc[mt][nt][3];
            if (MODE == 1) {
                float b0 = bias[c0], b1 = bias[c0 + 1];
                v0 += b0; v1 += b1; v2 += b0; v3 += b1;
            }
            if (MODE == 2) {
                v0 = 1.f / (1.f + __expf(-v0)); v1 = 1.f / (1.f + __expf(-v1));
                v2 = 1.f / (1.f + __expf(-v2)); v3 = 1.f / (1.f + __expf(-v3));
            }
            if (MODE == 0 || MODE == 2) {
                *(float2*)(C + (size_t)r0 * 1024 + c0) = make_float2(v0, v1);
                *(float2*)(C + (size_t)(r0 + 8) * 1024 + c0) = make_float2(v2, v3);
            } else {
                *(u32*)(Ch + (size_t)r0 * 1024 + c0) = prmt_hi(v0, v1);
                *(u32*)(Ch + (size_t)(r0 + 8) * 1024 + c0) = prmt_hi(v2, v3);
                *(u32*)(Cl + (size_t)r0 * 1024 + c0) =
                    pkbf2(__float2bfloat16(v0 - trunc_hi(v0)), __float2bfloat16(v1 - trunc_hi(v1)));
                *(u32*)(Cl + (size_t)(r0 + 8) * 1024 + c0) =
                    pkbf2(__float2bfloat16(v2 - trunc_hi(v2)), __float2bfloat16(v3 - trunc_hi(v3)));
            }
        }
    }
}

// ---------------- fused projections q,k,v,g (HMMA, pipelined) ---------------
__global__ __launch_bounds__(256) void proj_tc_kernel(const float* __restrict__ bq) {
    const int bm0 = blockIdx.y * 128, bn0 = blockIdx.x * 128;
    switch (blockIdx.z) {
        case 0: hmma_tile<1>(g_s_hi, g_s_lo, g_wq_hi, g_wq_lo, nullptr, g_qh, g_ql, bq, bm0, bn0, 0, 16); break;
        case 1: hmma_tile<3>(g_ki_hi, g_ki_lo, g_wk_hi, g_wk_lo, nullptr, g_kh, g_kl, nullptr, bm0, bn0, 0, 16); break;
        case 2: hmma_tile<3>(g_ki_hi, g_ki_lo, g_wv_hi, g_wv_lo, nullptr, g_vh, g_vl, nullptr, bm0, bn0, 0, 16); break;
        default: hmma_tile<2>(g_s_hi, g_s_lo, g_wg_hi, g_wg_lo, g_g, nullptr, nullptr, nullptr, bm0, bn0, 0, 16); break;
    }
}

// ---------------- output GEMM: out = (g*o) @ Wo^T (split-K2) ----------------
__global__ __launch_bounds__(256) void out_tc_kernel() {
    const int kz = blockIdx.z;
    hmma_tile<0>(g_ot_hi, g_ot_lo, g_wo_hi, g_wo_lo, g_part[kz], nullptr, nullptr, nullptr,
                 blockIdx.y * 128, blockIdx.x * 128, kz * 8, 8);
}
__global__ __launch_bounds__(256) void out_add_kernel(float* __restrict__ out) {
    size_t i = ((size_t)blockIdx.x * 256 + threadIdx.x) * 4;
    float4 a = *(const float4*)(g_part[0] + i);
    float4 b = *(const float4*)(g_part[1] + i);
    *(float4*)(out + i) = make_float4(a.x + b.x, a.y + b.y, a.z + b.z, a.w + b.w);
}

// ---------------- pair-bias projection z[h][i][j] + mask --------------------
__global__ __launch_bounds__(64) void z_kernel(const float* __restrict__ bias,
                                               const float* __restrict__ Wz,
                                               const float* __restrict__ mask) {
    __shared__ float sb[64 * 132];
    __shared__ float swz[128 * 16];
    const int tid = threadIdx.x;
    const size_t p0 = (size_t)blockIdx.x * 64;

    for (int idx = tid; idx < 128 * 16; idx += 64) swz[idx] = Wz[idx];
#pragma unroll
    for (int u = 0; u < 32; u++) {
        int lin = tid + u * 64;
        int pr = lin >> 5;
        int pc = (lin & 31) << 2;
        float4 v = *(const float4*)(bias + ((p0 + pr) << 7) + pc);
        *(float4*)&sb[pr * 132 + pc] = v;
    }
    __syncthreads();

    const int hg = tid & 3;
    const int pg = tid >> 2;
    float acc[4][4];
#pragma unroll
    for (int i = 0; i < 4; i++)
#pragma unroll
        for (int q = 0; q < 4; q++) acc[i][q] = 0.f;

#pragma unroll 4
    for (int c = 0; c < 128; c++) {
        float w[4];
        *(float4*)w = *(const float4*)&swz[c * 16 + hg * 4];
#pragma unroll
        for (int i = 0; i < 4; i++) {
            float bv = sb[(pg + 16 * i) * 132 + c];
            acc[i][0] += bv * w[0];
            acc[i][1] += bv * w[1];
            acc[i][2] += bv * w[2];
            acc[i][3] += bv * w[3];
        }
    }

#pragma unroll
    for (int i = 0; i < 4; i++) {
        size_t pair = p0 + pg + 16 * i;
        int j = (int)(pair & 1023);
        float madd = (1.f - mask[j]) * (-1000000.f);
#pragma unroll
        for (int q = 0; q < 4; q++) {
            int hh = hg * 4 + q;
            g_z[(size_t)hh * 1048576 + pair] = acc[i][q] + madd;
        }
    }
}

// ---------------- HMMA flash attention (pipelined) + fused gating -----------
// grid (8 i-blocks, 16 heads), 256 threads (8 warps x 16 query rows).
// smem: Q hi/lo 0..32K; K/V stages at 32K + s*32K (Kh,Kl,Vh,Vl 8KB each)
__device__ __forceinline__ void attn_ldkv(char* smc, int stage, int j0g, int h, int tid) {
    const u32 base = smem_u32(smc) + 32768 + stage * 32768;
#pragma unroll
    for (int u = 0; u < 2; u++) {
        int lin = tid + u * 256;
        int row = lin >> 3, ch = lin & 7;
        u32 sw = (u32)(row * 128) + ((u32)(ch ^ (row & 7)) << 4);
        size_t go = (size_t)(j0g + row) * 2048 + h * 128 + (ch << 4);
        cpa16(base + sw,         (const char*)g_kh + go);
        cpa16(base + 8192 + sw,  (const char*)g_kl + go);
        cpa16(base + 16384 + sw, (const char*)g_vh + go);
        cpa16(base + 24576 + sw, (const char*)g_vl + go);
    }
}

__global__ __launch_bounds__(256) void attn_kernel() {
    extern __shared__ char smc[];
    const int tid = threadIdx.x, lane = tid & 31, w = tid >> 5;
    const int h = blockIdx.y;
    const int i0 = blockIdx.x * 128;
    const u32 sb = smem_u32(smc);
    const u32 Qhs = sb;

    // stage Q hi/lo: 128 rows x 8 chunks of 16B each
#pragma unroll
    for (int u = 0; u < 4; u++) {
        int lin = tid + u * 256;
        int row = lin >> 3, ch = lin & 7;
        u32 sw16 = ((u32)(ch ^ (row & 7))) << 4;
        size_t go = (size_t)(i0 + row) * 2048 + h * 128 + (ch << 4);
        *(uint4*)(smc + row * 128 + sw16) = *(const uint4*)((const char*)g_qh + go);
        *(uint4*)(smc + 16384 + row * 128 + sw16) = *(const uint4*)((const char*)g_ql + go);
    }
    // prologue KV stage 0
    attn_ldkv(smc, 0, 0, h, tid);
    CPA_COMMIT();
    __syncthreads();

    // persistent Q fragments (warp rows w*16..w*16+15)
    u32 qh[4][4], ql[4][4];
    {
        int row = w * 16 + ((lane >> 3) & 1) * 8 + (lane & 7);
        u32 rbase = Qhs + row * 128;
#pragma unroll
        for (int kc = 0; kc < 4; kc++) {
            int ch = kc * 2 + (lane >> 4);
            u32 a = rbase + ((u32)(ch ^ (row & 7)) << 4);
            ldm_x4(a, qh[kc]);
            ldm_x4(a + 16384, ql[kc]);
        }
    }

    float m0 = -1e30f, m1 = -1e30f, l0 = 0.f, l1 = 0.f;
    float O[8][4];
#pragma unroll
    for (int nt = 0; nt < 8; nt++)
#pragma unroll
        for (int e = 0; e < 4; e++) O[nt][e] = 0.f;

    const float* zbase = g_z + (size_t)h * 1048576 +
                         (size_t)(i0 + w * 16 + (lane >> 2)) * 1024 + 2 * (lane & 3);

    for (int jt = 0; jt < 16; jt++) {
        const int j0g = jt * 64;
        if (jt + 1 < 16) {
            attn_ldkv(smc, (jt + 1) & 1, j0g + 64, h, tid);
            CPA_COMMIT();
            CPA_WAIT(1);
        } else {
            CPA_WAIT(0);
        }
        __syncthreads();
        const u32 Khs = sb + 32768 + (u32)(jt & 1) * 32768;
        const u32 Vhs = Khs + 16384;

        // ---- S = Q K^T (16 x 64 per warp), term-ordered ----
        float acc[8][4];
#pragma unroll
        for (int nt = 0; nt < 8; nt++)
#pragma unroll
            for (int e = 0; e < 4; e++) acc[nt][e] = 0.f;

#pragma unroll
        for (int kc = 0; kc < 4; kc++) {
            u32 kbh[4][4], kbl[4][4];
#pragma unroll
            for (int jp = 0; jp < 4; jp++) {
                int row = jp * 16 + (lane >> 4) * 8 + (lane & 7);
                int ch = kc * 2 + ((lane >> 3) & 1);
                u32 a = Khs + row * 128 + ((u32)(ch ^ (row & 7)) << 4);
                ldm_x4(a, kbh[jp]);
                ldm_x4(a + 8192, kbl[jp]);
            }
#pragma unroll
            for (int jp = 0; jp < 4; jp++)
#pragma unroll
                for (int hh = 0; hh < 2; hh++)
                    mma16816(acc[jp * 2 + hh], qh[kc], &kbh[jp][hh * 2]);
#pragma unroll
            for (int jp = 0; jp < 4; jp++)
#pragma unroll
                for (int hh = 0; hh < 2; hh++)
                    mma16816(acc[jp * 2 + hh], qh[kc], &kbl[jp][hh * 2]);
#pragma unroll
            for (int jp = 0; jp < 4; jp++)
#pragma unroll
                for (int hh = 0; hh < 2; hh++)
                    mma16816(acc[jp * 2 + hh], ql[kc], &kbh[jp][hh * 2]);
        }

        // ---- scale + z bias, online softmax ----
        const float* z0 = zbase + j0g;
        const float* z1 = z0 + 8192;     // +8 rows
        float mx0 = -1e30f, mx1 = -1e30f;
#pragma unroll
        for (int nt = 0; nt < 8; nt++) {
            float2 za = *(const float2*)(z0 + nt * 8);
            float2 zb = *(const float2*)(z1 + nt * 8);
            acc[nt][0] = acc[nt][0] * 0.125f + za.x;
            acc[nt][1] = acc[nt][1] * 0.125f + za.y;
            acc[nt][2] = acc[nt][2] * 0.125f + zb.x;
            acc[nt][3] = acc[nt][3] * 0.125f + zb.y;
            mx0 = fmaxf(mx0, fmaxf(acc[nt][0], acc[nt][1]));
            mx1 = fmaxf(mx1, fmaxf(acc[nt][2], acc[nt][3]));
        }
        mx0 = fmaxf(mx0, __shfl_xor_sync(0xffffffffu, mx0, 1));
        mx0 = fmaxf(mx0, __shfl_xor_sync(0xffffffffu, mx0, 2));
        mx1 = fmaxf(mx1, __shfl_xor_sync(0xffffffffu, mx1, 1));
        mx1 = fmaxf(mx1, __shfl_xor_sync(0xffffffffu, mx1, 2));
        float mn0 = fmaxf(m0, mx0), mn1 = fmaxf(m1, mx1);
        float cr0 = __expf(m0 - mn0), cr1 = __expf(m1 - mn1);
        float rs0 = 0.f, rs1 = 0.f;
#pragma unroll
        for (int nt = 0; nt < 8; nt++) {
            acc[nt][0] = __expf(acc[nt][0] - mn0);
            acc[nt][1] = __expf(acc[nt][1] - mn0);
            acc[nt][2] = __expf(acc[nt][2] - mn1);
            acc[nt][3] = __expf(acc[nt][3] - mn1);
            rs0 += acc[nt][0] + acc[nt][1];
            rs1 += acc[nt][2] + acc[nt][3];
        }
        rs0 += __shfl_xor_sync(0xffffffffu, rs0, 1);
        rs0 += __shfl_xor_sync(0xffffffffu, rs0, 2);
        rs1 += __shfl_xor_sync(0xffffffffu, rs1, 1);
        rs1 += __shfl_xor_sync(0xffffffffu, rs1, 2);
        l0 = l0 * cr0 + rs0; m0 = mn0;
        l1 = l1 * cr1 + rs1; m1 = mn1;
#pragma unroll
        for (int nt = 0; nt < 8; nt++) {
            O[nt][0] *= cr0; O[nt][1] *= cr0;
            O[nt][2] *= cr1; O[nt][3] *= cr1;
        }

        // ---- O += P V, term-ordered ----
#pragma unroll
        for (int kc = 0; kc < 4; kc++) {
            u32 pah[4], pal[4];
            {
                float* pa = acc[kc * 2];
                float* pb = acc[kc * 2 + 1];
                pah[0] = prmt_hi(pa[0], pa[1]);
                pah[1] = prmt_hi(pa[2], pa[3]);
                pah[2] = prmt_hi(pb[0], pb[1]);
                pah[3] = prmt_hi(pb[2], pb[3]);
                pal[0] = prmt_hi(pa[0] - trunc_hi(pa[0]), pa[1] - trunc_hi(pa[1]));
                pal[1] = prmt_hi(pa[2] - trunc_hi(pa[2]), pa[3] - trunc_hi(pa[3]));
                pal[2] = prmt_hi(pb[0] - trunc_hi(pb[0]), pb[1] - trunc_hi(pb[1]));
                pal[3] = prmt_hi(pb[2] - trunc_hi(pb[2]), pb[3] - trunc_hi(pb[3]));
            }
            u32 vbh[4][4], vbl[4][4];
#pragma unroll
            for (int dp = 0; dp < 4; dp++) {
                int row = kc * 16 + ((lane >> 3) & 1) * 8 + (lane & 7);
                int ch = dp * 2 + (lane >> 4);
                u32 a = Vhs + row * 128 + ((u32)(ch ^ (row & 7)) << 4);
                ldm_x4_t(a, vbh[dp]);
                ldm_x4_t(a + 8192, vbl[dp]);
            }
#pragma unroll
            for (int dp = 0; dp < 4; dp++)
#pragma unroll
                for (int hh = 0; hh < 2; hh++)
                    mma16816(O[dp * 2 + hh], pah, &vbh[dp][hh * 2]);
#pragma unroll
            for (int dp = 0; dp < 4; dp++)
#pragma unroll
                for (int hh = 0; hh < 2; hh++)
                    mma16816(O[dp * 2 + hh], pal, &vbh[dp][hh * 2]);
#pragma unroll
            for (int dp = 0; dp < 4; dp++)
#pragma unroll
                for (int hh = 0; hh < 2; hh++)
                    mma16816(O[dp * 2 + hh], pah, &vbl[dp][hh * 2]);
        }
        __syncthreads();
    }

    // ---- epilogue: normalize + gate + bf16 hi/lo split ----
    l0 += __shfl_xor_sync(0xffffffffu, l0, 1);
    l0 += __shfl_xor_sync(0xffffffffu, l0, 2);
    l1 += __shfl_xor_sync(0xffffffffu, l1, 1);
    l1 += __shfl_xor_sync(0xffffffffu, l1, 2);
    // rs was already quad-reduced each tile; the two shfl-adds above multiply
    // the row sum uniformly by 4 — compensate.
    l0 *= 0.25f; l1 *= 0.25f;
    float inv0 = 1.f / l0, inv1 = 1.f / l1;
    const int rg0 = i0 + w * 16 + (lane >> 2);
    const int cb = h * 64 + 2 * (lane & 3);
#pragma unroll
    for (int nt = 0; nt < 8; nt++) {
        int c = cb + nt * 8;
        float2 ga = *(const float2*)(g_g + (size_t)rg0 * 1024 + c);
        float2 gb = *(const float2*)(g_g + (size_t)(rg0 + 8) * 1024 + c);
        float o0 = O[nt][0] * inv0 * ga.x;
        float o1 = O[nt][1] * inv0 * ga.y;
        float o2 = O[nt][2] * inv1 * gb.x;
        float o3 = O[nt][3] * inv1 * gb.y;
        *(u32*)(g_ot_hi + (size_t)rg0 * 1024 + c) = prmt_hi(o0, o1);
        *(u32*)(g_ot_hi + (size_t)(rg0 + 8) * 1024 + c) = prmt_hi(o2, o3);
        *(u32*)(g_ot_lo + (size_t)rg0 * 1024 + c) =
            pkbf2(__float2bfloat16(o0 - trunc_hi(o0)), __float2bfloat16(o1 - trunc_hi(o1)));
        *(u32*)(g_ot_lo + (size_t)(rg0 + 8) * 1024 + c) =
            pkbf2(__float2bfloat16(o2 - trunc_hi(o2)), __float2bfloat16(o3 - trunc_hi(o3)));
    }
}

// ---------------- launch ----------------------------------------------------
extern "C" void kernel_launch(void* const* d_in, const int* in_sizes, int n_in,
                              void* d_out, int out_size) {
    const float* s    = (const float*)d_in[0];
    const float* kin  = (const float*)d_in[1];
    const float* mask = (const float*)d_in[2];
    const float* bias = (const float*)d_in[3];
    const float* Wq   = (const float*)d_in[4];
    const float* bq   = (const float*)d_in[5];
    const float* Wk   = (const float*)d_in[6];
    const float* Wv   = (const float*)d_in[7];
    const float* Wg   = (const float*)d_in[8];
    const float* Wo   = (const float*)d_in[9];
    const float* Wz   = (const float*)d_in[10];
    float* out = (float*)d_out;

    cudaFuncSetAttribute(proj_tc_kernel, cudaFuncAttributeMaxDynamicSharedMemorySize, 131072);
    cudaFuncSetAttribute(out_tc_kernel,  cudaFuncAttributeMaxDynamicSharedMemorySize, 131072);
    cudaFuncSetAttribute(attn_kernel,    cudaFuncAttributeMaxDynamicSharedMemorySize, 98304);

    split_kernel<<<dim3(1024, 7), 256>>>(s, kin, Wq, Wk, Wv, Wg, Wo);
    proj_tc_kernel<<<dim3(8, 8, 4), 256, 131072>>>(bq);
    z_kernel<<<16384, 64>>>(bias, Wz, mask);
    attn_kernel<<<dim3(8, 16), 256, 98304>>>();
    out_tc_kernel<<<dim3(8, 8, 2), 256, 131072>>>();
    out_add_kernel<<<1024, 256>>>(out);
}

// round 9
// speedup vs baseline: 1.8047x; 1.0180x over previous
#include <cuda_runtime.h>
#include <cuda_bf16.h>
#include <cstdint>
#include <math.h>

#define CS 1024
#define NH 16
#define HD 64

typedef unsigned int u32;

// ---------------- scratch (static device globals; no runtime allocation) ----
__device__ float g_g[1024 * 1024];
__device__ float g_z[16 * 1024 * 1024];   // [h][i][j]
__device__ float g_part[2][1024 * 1024];  // split-K partials for out GEMM

// bf16 hi/lo split operands for tensor-core GEMMs
__device__ __nv_bfloat16 g_s_hi[1024 * 1024],  g_s_lo[1024 * 1024];
__device__ __nv_bfloat16 g_ki_hi[1024 * 1024], g_ki_lo[1024 * 1024];
__device__ __nv_bfloat16 g_wq_hi[1024 * 1024], g_wq_lo[1024 * 1024];
__device__ __nv_bfloat16 g_wk_hi[1024 * 1024], g_wk_lo[1024 * 1024];
__device__ __nv_bfloat16 g_wv_hi[1024 * 1024], g_wv_lo[1024 * 1024];
__device__ __nv_bfloat16 g_wg_hi[1024 * 1024], g_wg_lo[1024 * 1024];
__device__ __nv_bfloat16 g_wo_hi[1024 * 1024], g_wo_lo[1024 * 1024];
__device__ __nv_bfloat16 g_ot_hi[1024 * 1024], g_ot_lo[1024 * 1024];
// q,k,v stored directly as bf16 hi/lo from projection epilogue
__device__ __nv_bfloat16 g_qh[1024 * 1024], g_ql[1024 * 1024];
__device__ __nv_bfloat16 g_kh[1024 * 1024], g_kl[1024 * 1024];
__device__ __nv_bfloat16 g_vh[1024 * 1024], g_vl[1024 * 1024];

// ---------------- helpers ---------------------------------------------------
__device__ __forceinline__ u32 smem_u32(const void* p) {
    u32 a;
    asm("{ .reg .u64 t; cvta.to.shared.u64 t, %1; cvt.u32.u64 %0, t; }" : "=r"(a) : "l"(p));
    return a;
}
__device__ __forceinline__ void ldm_x4(u32 addr, u32* r) {
    asm volatile("ldmatrix.sync.aligned.m8n8.x4.shared.b16 {%0,%1,%2,%3}, [%4];"
                 : "=r"(r[0]), "=r"(r[1]), "=r"(r[2]), "=r"(r[3]) : "r"(addr));
}
__device__ __forceinline__ void ldm_x4_t(u32 addr, u32* r) {
    asm volatile("ldmatrix.sync.aligned.m8n8.x4.trans.shared.b16 {%0,%1,%2,%3}, [%4];"
                 : "=r"(r[0]), "=r"(r[1]), "=r"(r[2]), "=r"(r[3]) : "r"(addr));
}
__device__ __forceinline__ void mma16816(float* c, const u32* a, const u32* b) {
    asm volatile(
        "mma.sync.aligned.m16n8k16.row.col.f32.bf16.bf16.f32 "
        "{%0,%1,%2,%3},{%4,%5,%6,%7},{%8,%9},{%0,%1,%2,%3};"
        : "+f"(c[0]), "+f"(c[1]), "+f"(c[2]), "+f"(c[3])
        : "r"(a[0]), "r"(a[1]), "r"(a[2]), "r"(a[3]), "r"(b[0]), "r"(b[1]));
}
__device__ __forceinline__ u32 pkbf2(__nv_bfloat16 a, __nv_bfloat16 b) {
    __nv_bfloat162 t = __halves2bfloat162(a, b);
    return *(u32*)&t;
}
__device__ __forceinline__ u32 prmt_hi(float a, float b) {
    u32 r;
    asm("prmt.b32 %0, %1, %2, 0x7632;"
        : "=r"(r) : "r"(__float_as_uint(a)), "r"(__float_as_uint(b)));
    return r;
}
__device__ __forceinline__ float trunc_hi(float a) {
    return __uint_as_float(__float_as_uint(a) & 0xFFFF0000u);
}
__device__ __forceinline__ void cpa16(u32 dst, const void* src) {
    asm volatile("cp.async.cg.shared.global [%0], [%1], 16;" :: "r"(dst), "l"(src));
}
#define CPA_COMMIT() asm volatile("cp.async.commit_group;" ::: "memory")
#define CPA_WAIT(n)  asm volatile("cp.async.wait_group %0;" :: "n"(n) : "memory")

// ---------------- fp32 -> bf16 hi/lo split ----------------------------------
__global__ __launch_bounds__(256) void split_kernel(const float* __restrict__ s,
                                                    const float* __restrict__ kin,
                                                    const float* __restrict__ wq,
                                                    const float* __restrict__ wk,
                                                    const float* __restrict__ wv,
                                                    const float* __restrict__ wg,
                                                    const float* __restrict__ wo) {
    const float* src;
    __nv_bfloat16 *dh, *dl;
    switch (blockIdx.y) {
        case 0: src = s;   dh = g_s_hi;  dl = g_s_lo;  break;
        case 1: src = kin; dh = g_ki_hi; dl = g_ki_lo; break;
        case 2: src = wq;  dh = g_wq_hi; dl = g_wq_lo; break;
        case 3: src = wk;  dh = g_wk_hi; dl = g_wk_lo; break;
        case 4: src = wv;  dh = g_wv_hi; dl = g_wv_lo; break;
        case 5: src = wg;  dh = g_wg_hi; dl = g_wg_lo; break;
        default: src = wo; dh = g_wo_hi; dl = g_wo_lo; break;
    }
    size_t i = ((size_t)blockIdx.x * 256 + threadIdx.x) * 4;
    float4 v = *(const float4*)(src + i);
    __nv_bfloat16 h0 = __float2bfloat16(v.x), h1 = __float2bfloat16(v.y);
    __nv_bfloat16 h2 = __float2bfloat16(v.z), h3 = __float2bfloat16(v.w);
    __nv_bfloat16 l0 = __float2bfloat16(v.x - __bfloat162float(h0));
    __nv_bfloat16 l1 = __float2bfloat16(v.y - __bfloat162float(h1));
    __nv_bfloat16 l2 = __float2bfloat16(v.z - __bfloat162float(h2));
    __nv_bfloat16 l3 = __float2bfloat16(v.w - __bfloat162float(h3));
    *(uint2*)(dh + i) = make_uint2(pkbf2(h0, h1), pkbf2(h2, h3));
    *(uint2*)(dl + i) = make_uint2(pkbf2(l0, l1), pkbf2(l2, l3));
}

// ---------------- pipelined HMMA GEMM tile: C[128,128] = A * B^T ------------
__device__ __forceinline__ void gemm_stage_ld(char* smem, int stage,
                                              const __nv_bfloat16* Ah,
                                              const __nv_bfloat16* Al,
                                              const __nv_bfloat16* Bh,
                                              const __nv_bfloat16* Bl,
                                              int bm0, int bn0, int kt, int tid) {
    const u32 sb = smem_u32(smem) + stage * 65536;
#pragma unroll
    for (int op = 0; op < 4; op++) {
        const __nv_bfloat16* src = (op == 0) ? Ah : (op == 1) ? Al : (op == 2) ? Bh : Bl;
        const int r0 = (op < 2) ? bm0 : bn0;
        const u32 d0 = sb + op * 16384;
#pragma unroll
        for (int u = 0; u < 4; u++) {
            int lin = tid + u * 256;
            int row = lin >> 3, ch = lin & 7;
            u32 sw = (u32)(row * 128) + ((u32)(ch ^ (row & 7)) << 4);
            cpa16(d0 + sw, src + (size_t)(r0 + row) * 1024 + kt * 64 + (ch << 3));
        }
    }
}

template <int MODE>
__device__ __forceinline__ void hmma_tile(const __nv_bfloat16* __restrict__ Ah,
                                          const __nv_bfloat16* __restrict__ Al,
                                          const __nv_bfloat16* __restrict__ Bh,
                                          const __nv_bfloat16* __restrict__ Bl,
                                          float* __restrict__ C,
                                          __nv_bfloat16* __restrict__ Ch,
                                          __nv_bfloat16* __restrict__ Cl,
                                          const float* __restrict__ bias,
                                          int bm0, int bn0, int kt0, int ktn) {
    extern __shared__ char smem[];
    const int tid = threadIdx.x;
    const int lane = tid & 31, wid = tid >> 5;
    const int wm = wid & 1, wn = wid >> 1;          // 2 x 4 warp grid
    const u32 sbase = smem_u32(smem);

    float acc[4][4][4];
#pragma unroll
    for (int mt = 0; mt < 4; mt++)
#pragma unroll
        for (int nt = 0; nt < 4; nt++)
#pragma unroll
            for (int e = 0; e < 4; e++) acc[mt][nt][e] = 0.f;

    gemm_stage_ld(smem, 0, Ah, Al, Bh, Bl, bm0, bn0, kt0, tid);
    CPA_COMMIT();

    for (int i = 0; i < ktn; i++) {
        if (i + 1 < ktn) {
            gemm_stage_ld(smem, (i + 1) & 1, Ah, Al, Bh, Bl, bm0, bn0, kt0 + i + 1, tid);
            CPA_COMMIT();
            CPA_WAIT(1);
        } else {
            CPA_WAIT(0);
        }
        __syncthreads();
        const u32 st = sbase + (u32)(i & 1) * 65536;

#pragma unroll
        for (int ks = 0; ks < 4; ks++) {
            u32 ah[4][4], al[4][4], bh[2][4], bl[2][4];
#pragma unroll
            for (int mt = 0; mt < 4; mt++) {
                int row = wm * 64 + mt * 16 + (lane & 15);
                int ch = ks * 2 + (lane >> 4);
                u32 addr = st + row * 128 + ((u32)(ch ^ (row & 7)) << 4);
                ldm_x4(addr, ah[mt]);
                ldm_x4(addr + 16384, al[mt]);
            }
#pragma unroll
            for (int nh = 0; nh < 2; nh++) {
                int row = wn * 32 + nh * 16 + (lane & 7) + ((lane >> 4) << 3);
                int ch = ks * 2 + ((lane >> 3) & 1);
                u32 addr = st + 32768 + row * 128 + ((u32)(ch ^ (row & 7)) << 4);
                ldm_x4(addr, bh[nh]);
                ldm_x4(addr + 16384, bl[nh]);
            }
#pragma unroll
            for (int mt = 0; mt < 4; mt++)
#pragma unroll
                for (int nt = 0; nt < 4; nt++)
                    mma16816(acc[mt][nt], ah[mt], &bh[nt >> 1][(nt & 1) * 2]);
#pragma unroll
            for (int mt = 0; mt < 4; mt++)
#pragma unroll
                for (int nt = 0; nt < 4; nt++)
                    mma16816(acc[mt][nt], ah[mt], &bl[nt >> 1][(nt & 1) * 2]);
#pragma unroll
            for (int mt = 0; mt < 4; mt++)
#pragma unroll
                for (int nt = 0; nt < 4; nt++)
                    mma16816(acc[mt][nt], al[mt], &bh[nt >> 1][(nt & 1) * 2]);
        }
        __syncthreads();
    }

#pragma unroll
    for (int mt = 0; mt < 4; mt++) {
        int r0 = bm0 + wm * 64 + mt * 16 + (lane >> 2);
#pragma unroll
        for (int nt = 0; nt < 4; nt++) {
            int c0 = bn0 + wn * 32 + nt * 8 + (lane & 3) * 2;
            float v0 = acc[mt][nt][0], v1 = acc[mt][nt][1];
            float v2 = acc[mt][nt][2], v3 = acc[mt][nt][3];
            if (MODE == 1) {
                float b0 = bias[c0], b1 = bias[c0 + 1];
                v0 += b0; v1 += b1; v2 += b0; v3 += b1;
            }
            if (MODE == 2) {
                v0 = 1.f / (1.f + __expf(-v0)); v1 = 1.f / (1.f + __expf(-v1));
                v2 = 1.f / (1.f + __expf(-v2)); v3 = 1.f / (1.f + __expf(-v3));
            }
            if (MODE == 0 || MODE == 2) {
                *(float2*)(C + (size_t)r0 * 1024 + c0) = make_float2(v0, v1);
                *(float2*)(C + (size_t)(r0 + 8) * 1024 + c0) = make_float2(v2, v3);
            } else {
                *(u32*)(Ch + (size_t)r0 * 1024 + c0) = prmt_hi(v0, v1);
                *(u32*)(Ch + (size_t)(r0 + 8) * 1024 + c0) = prmt_hi(v2, v3);
                *(u32*)(Cl + (size_t)r0 * 1024 + c0) =
                    pkbf2(__float2bfloat16(v0 - trunc_hi(v0)), __float2bfloat16(v1 - trunc_hi(v1)));
                *(u32*)(Cl + (size_t)(r0 + 8) * 1024 + c0) =
                    pkbf2(__float2bfloat16(v2 - trunc_hi(v2)), __float2bfloat16(v3 - trunc_hi(v3)));
            }
        }
    }
}

// ---------------- fused projections q,k,v,g (HMMA, pipelined) ---------------
__global__ __launch_bounds__(256) void proj_tc_kernel(const float* __restrict__ bq) {
    const int bm0 = blockIdx.y * 128, bn0 = blockIdx.x * 128;
    switch (blockIdx.z) {
        case 0: hmma_tile<1>(g_s_hi, g_s_lo, g_wq_hi, g_wq_lo, nullptr, g_qh, g_ql, bq, bm0, bn0, 0, 16); break;
        case 1: hmma_tile<3>(g_ki_hi, g_ki_lo, g_wk_hi, g_wk_lo, nullptr, g_kh, g_kl, nullptr, bm0, bn0, 0, 16); break;
        case 2: hmma_tile<3>(g_ki_hi, g_ki_lo, g_wv_hi, g_wv_lo, nullptr, g_vh, g_vl, nullptr, bm0, bn0, 0, 16); break;
        default: hmma_tile<2>(g_s_hi, g_s_lo, g_wg_hi, g_wg_lo, g_g, nullptr, nullptr, nullptr, bm0, bn0, 0, 16); break;
    }
}

// ---------------- output GEMM: out = (g*o) @ Wo^T (split-K2) ----------------
__global__ __launch_bounds__(256) void out_tc_kernel() {
    const int kz = blockIdx.z;
    hmma_tile<0>(g_ot_hi, g_ot_lo, g_wo_hi, g_wo_lo, g_part[kz], nullptr, nullptr, nullptr,
                 blockIdx.y * 128, blockIdx.x * 128, kz * 8, 8);
}
__global__ __launch_bounds__(256) void out_add_kernel(float* __restrict__ out) {
    size_t i = ((size_t)blockIdx.x * 256 + threadIdx.x) * 4;
    float4 a = *(const float4*)(g_part[0] + i);
    float4 b = *(const float4*)(g_part[1] + i);
    *(float4*)(out + i) = make_float4(a.x + b.x, a.y + b.y, a.z + b.z, a.w + b.w);
}

// ---------------- pair-bias projection z[h][i][j] + mask --------------------
__global__ __launch_bounds__(64) void z_kernel(const float* __restrict__ bias,
                                               const float* __restrict__ Wz,
                                               const float* __restrict__ mask) {
    __shared__ float sb[64 * 132];
    __shared__ float swz[128 * 16];
    const int tid = threadIdx.x;
    const size_t p0 = (size_t)blockIdx.x * 64;

    for (int idx = tid; idx < 128 * 16; idx += 64) swz[idx] = Wz[idx];
#pragma unroll
    for (int u = 0; u < 32; u++) {
        int lin = tid + u * 64;
        int pr = lin >> 5;
        int pc = (lin & 31) << 2;
        float4 v = *(const float4*)(bias + ((p0 + pr) << 7) + pc);
        *(float4*)&sb[pr * 132 + pc] = v;
    }
    __syncthreads();

    const int hg = tid & 3;
    const int pg = tid >> 2;
    float acc[4][4];
#pragma unroll
    for (int i = 0; i < 4; i++)
#pragma unroll
        for (int q = 0; q < 4; q++) acc[i][q] = 0.f;

#pragma unroll 4
    for (int c = 0; c < 128; c++) {
        float w[4];
        *(float4*)w = *(const float4*)&swz[c * 16 + hg * 4];
#pragma unroll
        for (int i = 0; i < 4; i++) {
            float bv = sb[(pg + 16 * i) * 132 + c];
            acc[i][0] += bv * w[0];
            acc[i][1] += bv * w[1];
            acc[i][2] += bv * w[2];
            acc[i][3] += bv * w[3];
        }
    }

#pragma unroll
    for (int i = 0; i < 4; i++) {
        size_t pair = p0 + pg + 16 * i;
        int j = (int)(pair & 1023);
        float madd = (1.f - mask[j]) * (-1000000.f);
#pragma unroll
        for (int q = 0; q < 4; q++) {
            int hh = hg * 4 + q;
            g_z[(size_t)hh * 1048576 + pair] = acc[i][q] + madd;
        }
    }
}

// ---------------- HMMA flash attention (pipelined, BM=64, 2 CTA/SM) ---------
// grid (16 i-blocks, 16 heads), 128 threads (4 warps x 16 query rows).
// smem: Q hi 0..8K, Q lo 8K..16K; K/V stages at 16K + s*32K (Kh,Kl,Vh,Vl 8K each)
__device__ __forceinline__ void attn_ldkv(char* smc, int stage, int j0g, int h, int tid) {
    const u32 base = smem_u32(smc) + 16384 + stage * 32768;
#pragma unroll
    for (int u = 0; u < 4; u++) {
        int lin = tid + u * 128;
        int row = lin >> 3, ch = lin & 7;
        u32 sw = (u32)(row * 128) + ((u32)(ch ^ (row & 7)) << 4);
        size_t go = (size_t)(j0g + row) * 2048 + h * 128 + (ch << 4);
        cpa16(base + sw,         (const char*)g_kh + go);
        cpa16(base + 8192 + sw,  (const char*)g_kl + go);
        cpa16(base + 16384 + sw, (const char*)g_vh + go);
        cpa16(base + 24576 + sw, (const char*)g_vl + go);
    }
}

__global__ __launch_bounds__(128) void attn_kernel() {
    extern __shared__ char smc[];
    const int tid = threadIdx.x, lane = tid & 31, w = tid >> 5;
    const int h = blockIdx.y;
    const int i0 = blockIdx.x * 64;
    const u32 sb = smem_u32(smc);
    const u32 Qhs = sb;

    // stage Q hi/lo: 64 rows x 8 chunks of 16B each
#pragma unroll
    for (int u = 0; u < 4; u++) {
        int lin = tid + u * 128;
        int row = lin >> 3, ch = lin & 7;
        u32 sw16 = ((u32)(ch ^ (row & 7))) << 4;
        size_t go = (size_t)(i0 + row) * 2048 + h * 128 + (ch << 4);
        *(uint4*)(smc + row * 128 + sw16) = *(const uint4*)((const char*)g_qh + go);
        *(uint4*)(smc + 8192 + row * 128 + sw16) = *(const uint4*)((const char*)g_ql + go);
    }
    attn_ldkv(smc, 0, 0, h, tid);
    CPA_COMMIT();
    __syncthreads();

    // persistent Q fragments (warp rows w*16..w*16+15)
    u32 qh[4][4], ql[4][4];
    {
        int row = w * 16 + ((lane >> 3) & 1) * 8 + (lane & 7);
        u32 rbase = Qhs + row * 128;
#pragma unroll
        for (int kc = 0; kc < 4; kc++) {
            int ch = kc * 2 + (lane >> 4);
            u32 a = rbase + ((u32)(ch ^ (row & 7)) << 4);
            ldm_x4(a, qh[kc]);
            ldm_x4(a + 8192, ql[kc]);
        }
    }

    float m0 = -1e30f, m1 = -1e30f, l0 = 0.f, l1 = 0.f;
    float O[8][4];
#pragma unroll
    for (int nt = 0; nt < 8; nt++)
#pragma unroll
        for (int e = 0; e < 4; e++) O[nt][e] = 0.f;

    const float* zbase = g_z + (size_t)h * 1048576 +
                         (size_t)(i0 + w * 16 + (lane >> 2)) * 1024 + 2 * (lane & 3);

    for (int jt = 0; jt < 16; jt++) {
        const int j0g = jt * 64;
        if (jt + 1 < 16) {
            attn_ldkv(smc, (jt + 1) & 1, j0g + 64, h, tid);
            CPA_COMMIT();
            CPA_WAIT(1);
        } else {
            CPA_WAIT(0);
        }
        __syncthreads();
        const u32 Khs = sb + 16384 + (u32)(jt & 1) * 32768;
        const u32 Vhs = Khs + 16384;

        // ---- S = Q K^T (16 x 64 per warp), term-ordered ----
        float acc[8][4];
#pragma unroll
        for (int nt = 0; nt < 8; nt++)
#pragma unroll
            for (int e = 0; e < 4; e++) acc[nt][e] = 0.f;

#pragma unroll
        for (int kc = 0; kc < 4; kc++) {
            u32 kbh[4][4], kbl[4][4];
#pragma unroll
            for (int jp = 0; jp < 4; jp++) {
                int row = jp * 16 + (lane >> 4) * 8 + (lane & 7);
                int ch = kc * 2 + ((lane >> 3) & 1);
                u32 a = Khs + row * 128 + ((u32)(ch ^ (row & 7)) << 4);
                ldm_x4(a, kbh[jp]);
                ldm_x4(a + 8192, kbl[jp]);
            }
#pragma unroll
            for (int jp = 0; jp < 4; jp++)
#pragma unroll
                for (int hh = 0; hh < 2; hh++)
                    mma16816(acc[jp * 2 + hh], qh[kc], &kbh[jp][hh * 2]);
#pragma unroll
            for (int jp = 0; jp < 4; jp++)
#pragma unroll
                for (int hh = 0; hh < 2; hh++)
                    mma16816(acc[jp * 2 + hh], qh[kc], &kbl[jp][hh * 2]);
#pragma unroll
            for (int jp = 0; jp < 4; jp++)
#pragma unroll
                for (int hh = 0; hh < 2; hh++)
                    mma16816(acc[jp * 2 + hh], ql[kc], &kbh[jp][hh * 2]);
        }

        // ---- scale + z bias, online softmax ----
        const float* z0 = zbase + j0g;
        const float* z1 = z0 + 8192;     // +8 rows
        float mx0 = -1e30f, mx1 = -1e30f;
#pragma unroll
        for (int nt = 0; nt < 8; nt++) {
            float2 za = *(const float2*)(z0 + nt * 8);
            float2 zb = *(const float2*)(z1 + nt * 8);
            acc[nt][0] = acc[nt][0] * 0.125f + za.x;
            acc[nt][1] = acc[nt][1] * 0.125f + za.y;
            acc[nt][2] = acc[nt][2] * 0.125f + zb.x;
            acc[nt][3] = acc[nt][3] * 0.125f + zb.y;
            mx0 = fmaxf(mx0, fmaxf(acc[nt][0], acc[nt][1]));
            mx1 = fmaxf(mx1, fmaxf(acc[nt][2], acc[nt][3]));
        }
        mx0 = fmaxf(mx0, __shfl_xor_sync(0xffffffffu, mx0, 1));
        mx0 = fmaxf(mx0, __shfl_xor_sync(0xffffffffu, mx0, 2));
        mx1 = fmaxf(mx1, __shfl_xor_sync(0xffffffffu, mx1, 1));
        mx1 = fmaxf(mx1, __shfl_xor_sync(0xffffffffu, mx1, 2));
        float mn0 = fmaxf(m0, mx0), mn1 = fmaxf(m1, mx1);
        float cr0 = __expf(m0 - mn0), cr1 = __expf(m1 - mn1);
        float rs0 = 0.f, rs1 = 0.f;
#pragma unroll
        for (int nt = 0; nt < 8; nt++) {
            acc[nt][0] = __expf(acc[nt][0] - mn0);
            acc[nt][1] = __expf(acc[nt][1] - mn0);
            acc[nt][2] = __expf(acc[nt][2] - mn1);
            acc[nt][3] = __expf(acc[nt][3] - mn1);
            rs0 += acc[nt][0] + acc[nt][1];
            rs1 += acc[nt][2] + acc[nt][3];
        }
        rs0 += __shfl_xor_sync(0xffffffffu, rs0, 1);
        rs0 += __shfl_xor_sync(0xffffffffu, rs0, 2);
        rs1 += __shfl_xor_sync(0xffffffffu, rs1, 1);
        rs1 += __shfl_xor_sync(0xffffffffu, rs1, 2);
        l0 = l0 * cr0 + rs0; m0 = mn0;
        l1 = l1 * cr1 + rs1; m1 = mn1;
#pragma unroll
        for (int nt = 0; nt < 8; nt++) {
            O[nt][0] *= cr0; O[nt][1] *= cr0;
            O[nt][2] *= cr1; O[nt][3] *= cr1;
        }

        // ---- O += P V, term-ordered ----
#pragma unroll
        for (int kc = 0; kc < 4; kc++) {
            u32 pah[4], pal[4];
            {
                float* pa = acc[kc * 2];
                float* pb = acc[kc * 2 + 1];
                pah[0] = prmt_hi(pa[0], pa[1]);
                pah[1] = prmt_hi(pa[2], pa[3]);
                pah[2] = prmt_hi(pb[0], pb[1]);
                pah[3] = prmt_hi(pb[2], pb[3]);
                pal[0] = prmt_hi(pa[0] - trunc_hi(pa[0]), pa[1] - trunc_hi(pa[1]));
                pal[1] = prmt_hi(pa[2] - trunc_hi(pa[2]), pa[3] - trunc_hi(pa[3]));
                pal[2] = prmt_hi(pb[0] - trunc_hi(pb[0]), pb[1] - trunc_hi(pb[1]));
                pal[3] = prmt_hi(pb[2] - trunc_hi(pb[2]), pb[3] - trunc_hi(pb[3]));
            }
            u32 vbh[4][4], vbl[4][4];
#pragma unroll
            for (int dp = 0; dp < 4; dp++) {
                int row = kc * 16 + ((lane >> 3) & 1) * 8 + (lane & 7);
                int ch = dp * 2 + (lane >> 4);
                u32 a = Vhs + row * 128 + ((u32)(ch ^ (row & 7)) << 4);
                ldm_x4_t(a, vbh[dp]);
                ldm_x4_t(a + 8192, vbl[dp]);
            }
#pragma unroll
            for (int dp = 0; dp < 4; dp++)
#pragma unroll
                for (int hh = 0; hh < 2; hh++)
                    mma16816(O[dp * 2 + hh], pah, &vbh[dp][hh * 2]);
#pragma unroll
            for (int dp = 0; dp < 4; dp++)
#pragma unroll
                for (int hh = 0; hh < 2; hh++)
                    mma16816(O[dp * 2 + hh], pal, &vbh[dp][hh * 2]);
#pragma unroll
            for (int dp = 0; dp < 4; dp++)
#pragma unroll
                for (int hh = 0; hh < 2; hh++)
                    mma16816(O[dp * 2 + hh], pah, &vbl[dp][hh * 2]);
        }
        __syncthreads();
    }

    // ---- epilogue: normalize + gate + bf16 hi/lo split ----
    l0 += __shfl_xor_sync(0xffffffffu, l0, 1);
    l0 += __shfl_xor_sync(0xffffffffu, l0, 2);
    l1 += __shfl_xor_sync(0xffffffffu, l1, 1);
    l1 += __shfl_xor_sync(0xffffffffu, l1, 2);
    // rs was already quad-reduced each tile; compensate uniform 4x.
    l0 *= 0.25f; l1 *= 0.25f;
    float inv0 = 1.f / l0, inv1 = 1.f / l1;
    const int rg0 = i0 + w * 16 + (lane >> 2);
    const int cb = h * 64 + 2 * (lane & 3);
#pragma unroll
    for (int nt = 0; nt < 8; nt++) {
        int c = cb + nt * 8;
        float2 ga = *(const float2*)(g_g + (size_t)rg0 * 1024 + c);
        float2 gb = *(const float2*)(g_g + (size_t)(rg0 + 8) * 1024 + c);
        float o0 = O[nt][0] * inv0 * ga.x;
        float o1 = O[nt][1] * inv0 * ga.y;
        float o2 = O[nt][2] * inv1 * gb.x;
        float o3 = O[nt][3] * inv1 * gb.y;
        *(u32*)(g_ot_hi + (size_t)rg0 * 1024 + c) = prmt_hi(o0, o1);
        *(u32*)(g_ot_hi + (size_t)(rg0 + 8) * 1024 + c) = prmt_hi(o2, o3);
        *(u32*)(g_ot_lo + (size_t)rg0 * 1024 + c) =
            pkbf2(__float2bfloat16(o0 - trunc_hi(o0)), __float2bfloat16(o1 - trunc_hi(o1)));
        *(u32*)(g_ot_lo + (size_t)(rg0 + 8) * 1024 + c) =
            pkbf2(__float2bfloat16(o2 - trunc_hi(o2)), __float2bfloat16(o3 - trunc_hi(o3)));
    }
}

// ---------------- launch ----------------------------------------------------
extern "C" void kernel_launch(void* const* d_in, const int* in_sizes, int n_in,
                              void* d_out, int out_size) {
    const float* s    = (const float*)d_in[0];
    const float* kin  = (const float*)d_in[1];
    const float* mask = (const float*)d_in[2];
    const float* bias = (const float*)d_in[3];
    const float* Wq   = (const float*)d_in[4];
    const float* bq   = (const float*)d_in[5];
    const float* Wk   = (const float*)d_in[6];
    const float* Wv   = (const float*)d_in[7];
    const float* Wg   = (const float*)d_in[8];
    const float* Wo   = (const float*)d_in[9];
    const float* Wz   = (const float*)d_in[10];
    float* out = (float*)d_out;

    // one-time stream/event setup (first call runs uncaptured; captured calls
    // reuse the handles — work per call is identical and deterministic)
    static cudaStream_t zstream = nullptr;
    static cudaEvent_t ev_fork = nullptr, ev_join = nullptr;
    if (zstream == nullptr) {
        cudaStreamCreateWithFlags(&zstream, cudaStreamNonBlocking);
        cudaEventCreateWithFlags(&ev_fork, cudaEventDisableTiming);
        cudaEventCreateWithFlags(&ev_join, cudaEventDisableTiming);
    }

    cudaFuncSetAttribute(proj_tc_kernel, cudaFuncAttributeMaxDynamicSharedMemorySize, 131072);
    cudaFuncSetAttribute(out_tc_kernel,  cudaFuncAttributeMaxDynamicSharedMemorySize, 131072);
    cudaFuncSetAttribute(attn_kernel,    cudaFuncAttributeMaxDynamicSharedMemorySize, 81920);

    // fork: z (DRAM-bound) runs concurrently with split+proj (tensor-bound)
    cudaEventRecord(ev_fork, 0);
    cudaStreamWaitEvent(zstream, ev_fork, 0);
    z_kernel<<<16384, 64, 0, zstream>>>(bias, Wz, mask);
    cudaEventRecord(ev_join, zstream);

    split_kernel<<<dim3(1024, 7), 256>>>(s, kin, Wq, Wk, Wv, Wg, Wo);
    proj_tc_kernel<<<dim3(8, 8, 4), 256, 131072>>>(bq);

    cudaStreamWaitEvent(0, ev_join, 0);
    attn_kernel<<<dim3(16, 16), 128, 81920>>>();
    out_tc_kernel<<<dim3(8, 8, 2), 256, 131072>>>();
    out_add_kernel<<<1024, 256>>>(out);
}

// round 11
// speedup vs baseline: 1.8144x; 1.0054x over previous
#include <cuda_runtime.h>
#include <cuda_bf16.h>
#include <cstdint>
#include <math.h>

#define CS 1024
#define NH 16
#define HD 64

typedef unsigned int u32;
typedef unsigned long long u64t;

// ---------------- scratch (static device globals; no runtime allocation) ----
__device__ float g_g[1024 * 1024];
__device__ float g_z[16 * 1024 * 1024];   // [h][i][j]
__device__ float g_part[2][1024 * 1024];  // split-K partials for out GEMM

// bf16 hi/lo split operands for tensor-core GEMMs
__device__ __nv_bfloat16 g_s_hi[1024 * 1024],  g_s_lo[1024 * 1024];
__device__ __nv_bfloat16 g_ki_hi[1024 * 1024], g_ki_lo[1024 * 1024];
__device__ __nv_bfloat16 g_wq_hi[1024 * 1024], g_wq_lo[1024 * 1024];
__device__ __nv_bfloat16 g_wk_hi[1024 * 1024], g_wk_lo[1024 * 1024];
__device__ __nv_bfloat16 g_wv_hi[1024 * 1024], g_wv_lo[1024 * 1024];
__device__ __nv_bfloat16 g_wg_hi[1024 * 1024], g_wg_lo[1024 * 1024];
__device__ __nv_bfloat16 g_wo_hi[1024 * 1024], g_wo_lo[1024 * 1024];
__device__ __nv_bfloat16 g_ot_hi[1024 * 1024], g_ot_lo[1024 * 1024];
// q,k,v stored directly as bf16 hi/lo from projection epilogue
__device__ __nv_bfloat16 g_qh[1024 * 1024], g_ql[1024 * 1024];
__device__ __nv_bfloat16 g_kh[1024 * 1024], g_kl[1024 * 1024];
__device__ __nv_bfloat16 g_vh[1024 * 1024], g_vl[1024 * 1024];

// ---------------- helpers ---------------------------------------------------
__device__ __forceinline__ u32 smem_u32(const void* p) {
    u32 a;
    asm("{ .reg .u64 t; cvta.to.shared.u64 t, %1; cvt.u32.u64 %0, t; }" : "=r"(a) : "l"(p));
    return a;
}
__device__ __forceinline__ void ldm_x4(u32 addr, u32* r) {
    asm volatile("ldmatrix.sync.aligned.m8n8.x4.shared.b16 {%0,%1,%2,%3}, [%4];"
                 : "=r"(r[0]), "=r"(r[1]), "=r"(r[2]), "=r"(r[3]) : "r"(addr));
}
__device__ __forceinline__ void ldm_x4_t(u32 addr, u32* r) {
    asm volatile("ldmatrix.sync.aligned.m8n8.x4.trans.shared.b16 {%0,%1,%2,%3}, [%4];"
                 : "=r"(r[0]), "=r"(r[1]), "=r"(r[2]), "=r"(r[3]) : "r"(addr));
}
__device__ __forceinline__ void mma16816(float* c, const u32* a, const u32* b) {
    asm volatile(
        "mma.sync.aligned.m16n8k16.row.col.f32.bf16.bf16.f32 "
        "{%0,%1,%2,%3},{%4,%5,%6,%7},{%8,%9},{%0,%1,%2,%3};"
        : "+f"(c[0]), "+f"(c[1]), "+f"(c[2]), "+f"(c[3])
        : "r"(a[0]), "r"(a[1]), "r"(a[2]), "r"(a[3]), "r"(b[0]), "r"(b[1]));
}
__device__ __forceinline__ u32 pkbf2(__nv_bfloat16 a, __nv_bfloat16 b) {
    __nv_bfloat162 t = __halves2bfloat162(a, b);
    return *(u32*)&t;
}
__device__ __forceinline__ u32 prmt_hi(float a, float b) {
    u32 r;
    asm("prmt.b32 %0, %1, %2, 0x7632;"
        : "=r"(r) : "r"(__float_as_uint(a)), "r"(__float_as_uint(b)));
    return r;
}
__device__ __forceinline__ float trunc_hi(float a) {
    return __uint_as_float(__float_as_uint(a) & 0xFFFF0000u);
}
__device__ __forceinline__ void cpa16(u32 dst, const void* src) {
    asm volatile("cp.async.cg.shared.global [%0], [%1], 16;" :: "r"(dst), "l"(src));
}
#define CPA_COMMIT() asm volatile("cp.async.commit_group;" ::: "memory")
#define CPA_WAIT(n)  asm volatile("cp.async.wait_group %0;" :: "n"(n) : "memory")

// packed f32x2 helpers (issue-bound z kernel only — low register pressure there)
__device__ __forceinline__ u64t pk2(float a, float b) {
    u64t r; asm("mov.b64 %0,{%1,%2};" : "=l"(r) : "f"(a), "f"(b)); return r;
}
__device__ __forceinline__ u64t dup2(float a) { return pk2(a, a); }
__device__ __forceinline__ float2 up2(u64t v) {
    float2 f; asm("mov.b64 {%0,%1},%2;" : "=f"(f.x), "=f"(f.y) : "l"(v)); return f;
}
__device__ __forceinline__ u64t fma2(u64t a, u64t b, u64t c) {
    u64t d; asm("fma.rn.f32x2 %0,%1,%2,%3;" : "=l"(d) : "l"(a), "l"(b), "l"(c)); return d;
}

// ---------------- fp32 -> bf16 hi/lo split ----------------------------------
__global__ __launch_bounds__(256) void split_kernel(const float* __restrict__ s,
                                                    const float* __restrict__ kin,
                                                    const float* __restrict__ wq,
                                                    const float* __restrict__ wk,
                                                    const float* __restrict__ wv,
                                                    const float* __restrict__ wg,
                                                    const float* __restrict__ wo) {
    const float* src;
    __nv_bfloat16 *dh, *dl;
    switch (blockIdx.y) {
        case 0: src = s;   dh = g_s_hi;  dl = g_s_lo;  break;
        case 1: src = kin; dh = g_ki_hi; dl = g_ki_lo; break;
        case 2: src = wq;  dh = g_wq_hi; dl = g_wq_lo; break;
        case 3: src = wk;  dh = g_wk_hi; dl = g_wk_lo; break;
        case 4: src = wv;  dh = g_wv_hi; dl = g_wv_lo; break;
        case 5: src = wg;  dh = g_wg_hi; dl = g_wg_lo; break;
        default: src = wo; dh = g_wo_hi; dl = g_wo_lo; break;
    }
    size_t i = ((size_t)blockIdx.x * 256 + threadIdx.x) * 4;
    float4 v = *(const float4*)(src + i);
    __nv_bfloat16 h0 = __float2bfloat16(v.x), h1 = __float2bfloat16(v.y);
    __nv_bfloat16 h2 = __float2bfloat16(v.z), h3 = __float2bfloat16(v.w);
    __nv_bfloat16 l0 = __float2bfloat16(v.x - __bfloat162float(h0));
    __nv_bfloat16 l1 = __float2bfloat16(v.y - __bfloat162float(h1));
    __nv_bfloat16 l2 = __float2bfloat16(v.z - __bfloat162float(h2));
    __nv_bfloat16 l3 = __float2bfloat16(v.w - __bfloat162float(h3));
    *(uint2*)(dh + i) = make_uint2(pkbf2(h0, h1), pkbf2(h2, h3));
    *(uint2*)(dl + i) = make_uint2(pkbf2(l0, l1), pkbf2(l2, l3));
}

// ---------------- pipelined HMMA GEMM tile: C[128,128] = A * B^T ------------
__device__ __forceinline__ void gemm_stage_ld(char* smem, int stage,
                                              const __nv_bfloat16* Ah,
                                              const __nv_bfloat16* Al,
                                              const __nv_bfloat16* Bh,
                                              const __nv_bfloat16* Bl,
                                              int bm0, int bn0, int kt, int tid) {
    const u32 sb = smem_u32(smem) + stage * 65536;
#pragma unroll
    for (int op = 0; op < 4; op++) {
        const __nv_bfloat16* src = (op == 0) ? Ah : (op == 1) ? Al : (op == 2) ? Bh : Bl;
        const int r0 = (op < 2) ? bm0 : bn0;
        const u32 d0 = sb + op * 16384;
#pragma unroll
        for (int u = 0; u < 4; u++) {
            int lin = tid + u * 256;
            int row = lin >> 3, ch = lin & 7;
            u32 sw = (u32)(row * 128) + ((u32)(ch ^ (row & 7)) << 4);
            cpa16(d0 + sw, src + (size_t)(r0 + row) * 1024 + kt * 64 + (ch << 3));
        }
    }
}

template <int MODE>
__device__ __forceinline__ void hmma_tile(const __nv_bfloat16* __restrict__ Ah,
                                          const __nv_bfloat16* __restrict__ Al,
                                          const __nv_bfloat16* __restrict__ Bh,
                                          const __nv_bfloat16* __restrict__ Bl,
                                          float* __restrict__ C,
                                          __nv_bfloat16* __restrict__ Ch,
                                          __nv_bfloat16* __restrict__ Cl,
                                          const float* __restrict__ bias,
                                          int bm0, int bn0, int kt0, int ktn) {
    extern __shared__ char smem[];
    const int tid = threadIdx.x;
    const int lane = tid & 31, wid = tid >> 5;
    const int wm = wid & 1, wn = wid >> 1;          // 2 x 4 warp grid
    const u32 sbase = smem_u32(smem);

    float acc[4][4][4];
#pragma unroll
    for (int mt = 0; mt < 4; mt++)
#pragma unroll
        for (int nt = 0; nt < 4; nt++)
#pragma unroll
            for (int e = 0; e < 4; e++) acc[mt][nt][e] = 0.f;

    gemm_stage_ld(smem, 0, Ah, Al, Bh, Bl, bm0, bn0, kt0, tid);
    CPA_COMMIT();

    for (int i = 0; i < ktn; i++) {
        if (i + 1 < ktn) {
            gemm_stage_ld(smem, (i + 1) & 1, Ah, Al, Bh, Bl, bm0, bn0, kt0 + i + 1, tid);
            CPA_COMMIT();
            CPA_WAIT(1);
        } else {
            CPA_WAIT(0);
        }
        __syncthreads();
        const u32 st = sbase + (u32)(i & 1) * 65536;

#pragma unroll
        for (int ks = 0; ks < 4; ks++) {
            u32 ah[4][4], al[4][4], bh[2][4], bl[2][4];
#pragma unroll
            for (int mt = 0; mt < 4; mt++) {
                int row = wm * 64 + mt * 16 + (lane & 15);
                int ch = ks * 2 + (lane >> 4);
                u32 addr = st + row * 128 + ((u32)(ch ^ (row & 7)) << 4);
                ldm_x4(addr, ah[mt]);
                ldm_x4(addr + 16384, al[mt]);
            }
#pragma unroll
            for (int nh = 0; nh < 2; nh++) {
                int row = wn * 32 + nh * 16 + (lane & 7) + ((lane >> 4) << 3);
                int ch = ks * 2 + ((lane >> 3) & 1);
                u32 addr = st + 32768 + row * 128 + ((u32)(ch ^ (row & 7)) << 4);
                ldm_x4(addr, bh[nh]);
                ldm_x4(addr + 16384, bl[nh]);
            }
#pragma unroll
            for (int mt = 0; mt < 4; mt++)
#pragma unroll
                for (int nt = 0; nt < 4; nt++)
                    mma16816(acc[mt][nt], ah[mt], &bh[nt >> 1][(nt & 1) * 2]);
#pragma unroll
            for (int mt = 0; mt < 4; mt++)
#pragma unroll
                for (int nt = 0; nt < 4; nt++)
                    mma16816(acc[mt][nt], ah[mt], &bl[nt >> 1][(nt & 1) * 2]);
#pragma unroll
            for (int mt = 0; mt < 4; mt++)
#pragma unroll
                for (int nt = 0; nt < 4; nt++)
                    mma16816(acc[mt][nt], al[mt], &bh[nt >> 1][(nt & 1) * 2]);
        }
        __syncthreads();
    }

#pragma unroll
    for (int mt = 0; mt < 4; mt++) {
        int r0 = bm0 + wm * 64 + mt * 16 + (lane >> 2);
#pragma unroll
        for (int nt = 0; nt < 4; nt++) {
            int c0 = bn0 + wn * 32 + nt * 8 + (lane & 3) * 2;
            float v0 = acc[mt][nt][0], v1 = acc[mt][nt][1];
            float v2 = acc[mt][nt][2], v3 = acc[mt][nt][3];
            if (MODE == 1) {
                float b0 = bias[c0], b1 = bias[c0 + 1];
                v0 += b0; v1 += b1; v2 += b0; v3 += b1;
            }
            if (MODE == 2) {
                v0 = 1.f / (1.f + __expf(-v0)); v1 = 1.f / (1.f + __expf(-v1));
                v2 = 1.f / (1.f + __expf(-v2)); v3 = 1.f / (1.f + __expf(-v3));
            }
            if (MODE == 0 || MODE == 2) {
                *(float2*)(C + (size_t)r0 * 1024 + c0) = make_float2(v0, v1);
                *(float2*)(C + (size_t)(r0 + 8) * 1024 + c0) = make_float2(v2, v3);
            } else {
                *(u32*)(Ch + (size_t)r0 * 1024 + c0) = prmt_hi(v0, v1);
                *(u32*)(Ch + (size_t)(r0 + 8) * 1024 + c0) = prmt_hi(v2, v3);
                *(u32*)(Cl + (size_t)r0 * 1024 + c0) =
                    pkbf2(__float2bfloat16(v0 - trunc_hi(v0)), __float2bfloat16(v1 - trunc_hi(v1)));
                *(u32*)(Cl + (size_t)(r0 + 8) * 1024 + c0) =
                    pkbf2(__float2bfloat16(v2 - trunc_hi(v2)), __float2bfloat16(v3 - trunc_hi(v3)));
            }
        }
    }
}

// ---------------- fused projections q,k,v,g (HMMA, pipelined) ---------------
__global__ __launch_bounds__(256) void proj_tc_kernel(const float* __restrict__ bq) {
    const int bm0 = blockIdx.y * 128, bn0 = blockIdx.x * 128;
    switch (blockIdx.z) {
        case 0: hmma_tile<1>(g_s_hi, g_s_lo, g_wq_hi, g_wq_lo, nullptr, g_qh, g_ql, bq, bm0, bn0, 0, 16); break;
        case 1: hmma_tile<3>(g_ki_hi, g_ki_lo, g_wk_hi, g_wk_lo, nullptr, g_kh, g_kl, nullptr, bm0, bn0, 0, 16); break;
        case 2: hmma_tile<3>(g_ki_hi, g_ki_lo, g_wv_hi, g_wv_lo, nullptr, g_vh, g_vl, nullptr, bm0, bn0, 0, 16); break;
        default: hmma_tile<2>(g_s_hi, g_s_lo, g_wg_hi, g_wg_lo, g_g, nullptr, nullptr, nullptr, bm0, bn0, 0, 16); break;
    }
}

// ---------------- output GEMM: out = (g*o) @ Wo^T (split-K2) ----------------
__global__ __launch_bounds__(256) void out_tc_kernel() {
    const int kz = blockIdx.z;
    hmma_tile<0>(g_ot_hi, g_ot_lo, g_wo_hi, g_wo_lo, g_part[kz], nullptr, nullptr, nullptr,
                 blockIdx.y * 128, blockIdx.x * 128, kz * 8, 8);
}
__global__ __launch_bounds__(256) void out_add_kernel(float* __restrict__ out) {
    size_t i = ((size_t)blockIdx.x * 256 + threadIdx.x) * 4;
    float4 a = *(const float4*)(g_part[0] + i);
    float4 b = *(const float4*)(g_part[1] + i);
    *(float4*)(out + i) = make_float4(a.x + b.x, a.y + b.y, a.z + b.z, a.w + b.w);
}

// ---------------- pair-bias projection z[h][i][j] + mask (FFMA2) ------------
// 1024 blocks x 256 threads; each block: 8 chunks of 128 pairs, cp.async
// double-buffered. Thread: 2 pairs x 4 heads, f32x2 inner loop.
// smem layout (floats): buf0[128*132], buf1[128*132], swz[128*16]
#define ZBUF (128 * 132)
__device__ __forceinline__ void z_stage(u32 sb, int stage, const float* __restrict__ bias,
                                        size_t p0c, int tid) {
    const u32 base = sb + (u32)stage * (ZBUF * 4);
#pragma unroll
    for (int u = 0; u < 16; u++) {
        int lin = tid + u * 256;
        int row = lin >> 5, col4 = lin & 31;
        cpa16(base + (u32)(row * 132 + col4 * 4) * 4,
              bias + (p0c + row) * 128 + col4 * 4);
    }
}

__global__ __launch_bounds__(256) void z_kernel(const float* __restrict__ bias,
                                                const float* __restrict__ Wz,
                                                const float* __restrict__ mask) {
    extern __shared__ float zsm[];
    float* swz = zsm + 2 * ZBUF;
    const int tid = threadIdx.x;
    const u32 sb = smem_u32(zsm);
    const size_t p0 = (size_t)blockIdx.x * 1024;

    for (int idx = tid; idx < 128 * 16; idx += 256) swz[idx] = Wz[idx];

    z_stage(sb, 0, bias, p0, tid);
    CPA_COMMIT();

    const int hg = tid & 3;          // heads hg*4 .. hg*4+3
    const int pg = tid >> 2;         // pair slots pg, pg+64 within chunk

    for (int ch = 0; ch < 8; ch++) {
        if (ch + 1 < 8) {
            z_stage(sb, (ch + 1) & 1, bias, p0 + (size_t)(ch + 1) * 128, tid);
            CPA_COMMIT();
            CPA_WAIT(1);
        } else {
            CPA_WAIT(0);
        }
        __syncthreads();
        const float* buf = zsm + (ch & 1) * ZBUF;

        u64t a00 = 0, a01 = 0, a10 = 0, a11 = 0;   // [pair][head-pair]
        const float* r0 = buf + pg * 132;
        const float* r1 = buf + (pg + 64) * 132;
#pragma unroll 8
        for (int c = 0; c < 128; c++) {
            float4 w = *(const float4*)&swz[c * 16 + hg * 4];
            u64t w01 = pk2(w.x, w.y), w23 = pk2(w.z, w.w);
            u64t b0 = dup2(r0[c]);
            u64t b1 = dup2(r1[c]);
            a00 = fma2(b0, w01, a00);
            a01 = fma2(b0, w23, a01);
            a10 = fma2(b1, w01, a10);
            a11 = fma2(b1, w23, a11);
        }

        size_t pair0 = p0 + (size_t)ch * 128 + pg;
        size_t pair1 = pair0 + 64;
        float m0 = (1.f - mask[(int)(pair0 & 1023)]) * (-1000000.f);
        float m1 = (1.f - mask[(int)(pair1 & 1023)]) * (-1000000.f);
        float2 v00 = up2(a00), v01 = up2(a01), v10 = up2(a10), v11 = up2(a11);
        float z0[4] = {v00.x, v00.y, v01.x, v01.y};
        float z1[4] = {v10.x, v10.y, v11.x, v11.y};
#pragma unroll
        for (int q = 0; q < 4; q++) {
            g_z[(size_t)(hg * 4 + q) * 1048576 + pair0] = z0[q] + m0;
            g_z[(size_t)(hg * 4 + q) * 1048576 + pair1] = z1[q] + m1;
        }
        __syncthreads();   // buffer (ch&1) free for restage next iteration
    }
}

// ---------------- HMMA flash attention (pipelined, BM=64, 2 CTA/SM) ---------
// grid (16 i-blocks, 16 heads), 128 threads (4 warps x 16 query rows).
// smem: Q hi 0..8K, Q lo 8K..16K; K/V stages at 16K + s*32K (Kh,Kl,Vh,Vl 8K each)
__device__ __forceinline__ void attn_ldkv(char* smc, int stage, int j0g, int h, int tid) {
    const u32 base = smem_u32(smc) + 16384 + stage * 32768;
#pragma unroll
    for (int u = 0; u < 4; u++) {
        int lin = tid + u * 128;
        int row = lin >> 3, ch = lin & 7;
        u32 sw = (u32)(row * 128) + ((u32)(ch ^ (row & 7)) << 4);
        size_t go = (size_t)(j0g + row) * 2048 + h * 128 + (ch << 4);
        cpa16(base + sw,         (const char*)g_kh + go);
        cpa16(base + 8192 + sw,  (const char*)g_kl + go);
        cpa16(base + 16384 + sw, (const char*)g_vh + go);
        cpa16(base + 24576 + sw, (const char*)g_vl + go);
    }
}

__global__ __launch_bounds__(128) void attn_kernel() {
    extern __shared__ char smc[];
    const int tid = threadIdx.x, lane = tid & 31, w = tid >> 5;
    const int h = blockIdx.y;
    const int i0 = blockIdx.x * 64;
    const u32 sb = smem_u32(smc);
    const u32 Qhs = sb;

    // stage Q hi/lo: 64 rows x 8 chunks of 16B each
#pragma unroll
    for (int u = 0; u < 4; u++) {
        int lin = tid + u * 128;
        int row = lin >> 3, ch = lin & 7;
        u32 sw16 = ((u32)(ch ^ (row & 7))) << 4;
        size_t go = (size_t)(i0 + row) * 2048 + h * 128 + (ch << 4);
        *(uint4*)(smc + row * 128 + sw16) = *(const uint4*)((const char*)g_qh + go);
        *(uint4*)(smc + 8192 + row * 128 + sw16) = *(const uint4*)((const char*)g_ql + go);
    }
    attn_ldkv(smc, 0, 0, h, tid);
    CPA_COMMIT();
    __syncthreads();

    // persistent Q fragments (warp rows w*16..w*16+15)
    u32 qh[4][4], ql[4][4];
    {
        int row = w * 16 + ((lane >> 3) & 1) * 8 + (lane & 7);
        u32 rbase = Qhs + row * 128;
#pragma unroll
        for (int kc = 0; kc < 4; kc++) {
            int ch = kc * 2 + (lane >> 4);
            u32 a = rbase + ((u32)(ch ^ (row & 7)) << 4);
            ldm_x4(a, qh[kc]);
            ldm_x4(a + 8192, ql[kc]);
        }
    }

    float m0 = -1e30f, m1 = -1e30f, l0 = 0.f, l1 = 0.f;
    float O[8][4];
#pragma unroll
    for (int nt = 0; nt < 8; nt++)
#pragma unroll
        for (int e = 0; e < 4; e++) O[nt][e] = 0.f;

    const float* zbase = g_z + (size_t)h * 1048576 +
                         (size_t)(i0 + w * 16 + (lane >> 2)) * 1024 + 2 * (lane & 3);

    for (int jt = 0; jt < 16; jt++) {
        const int j0g = jt * 64;
        if (jt + 1 < 16) {
            attn_ldkv(smc, (jt + 1) & 1, j0g + 64, h, tid);
            CPA_COMMIT();
            CPA_WAIT(1);
        } else {
            CPA_WAIT(0);
        }
        __syncthreads();
        const u32 Khs = sb + 16384 + (u32)(jt & 1) * 32768;
        const u32 Vhs = Khs + 16384;

        // ---- S = Q K^T (16 x 64 per warp), term-ordered ----
        float acc[8][4];
#pragma unroll
        for (int nt = 0; nt < 8; nt++)
#pragma unroll
            for (int e = 0; e < 4; e++) acc[nt][e] = 0.f;

#pragma unroll
        for (int kc = 0; kc < 4; kc++) {
            u32 kbh[4][4], kbl[4][4];
#pragma unroll
            for (int jp = 0; jp < 4; jp++) {
                int row = jp * 16 + (lane >> 4) * 8 + (lane & 7);
                int ch = kc * 2 + ((lane >> 3) & 1);
                u32 a = Khs + row * 128 + ((u32)(ch ^ (row & 7)) << 4);
                ldm_x4(a, kbh[jp]);
                ldm_x4(a + 8192, kbl[jp]);
            }
#pragma unroll
            for (int jp = 0; jp < 4; jp++)
#pragma unroll
                for (int hh = 0; hh < 2; hh++)
                    mma16816(acc[jp * 2 + hh], qh[kc], &kbh[jp][hh * 2]);
#pragma unroll
            for (int jp = 0; jp < 4; jp++)
#pragma unroll
                for (int hh = 0; hh < 2; hh++)
                    mma16816(acc[jp * 2 + hh], qh[kc], &kbl[jp][hh * 2]);
#pragma unroll
            for (int jp = 0; jp < 4; jp++)
#pragma unroll
                for (int hh = 0; hh < 2; hh++)
                    mma16816(acc[jp * 2 + hh], ql[kc], &kbh[jp][hh * 2]);
        }

        // ---- scale + z bias, online softmax ----
        const float* z0 = zbase + j0g;
        const float* z1 = z0 + 8192;     // +8 rows
        float mx0 = -1e30f, mx1 = -1e30f;
#pragma unroll
        for (int nt = 0; nt < 8; nt++) {
            float2 za = *(const float2*)(z0 + nt * 8);
            float2 zb = *(const float2*)(z1 + nt * 8);
            acc[nt][0] = acc[nt][0] * 0.125f + za.x;
            acc[nt][1] = acc[nt][1] * 0.125f + za.y;
            acc[nt][2] = acc[nt][2] * 0.125f + zb.x;
            acc[nt][3] = acc[nt][3] * 0.125f + zb.y;
            mx0 = fmaxf(mx0, fmaxf(acc[nt][0], acc[nt][1]));
            mx1 = fmaxf(mx1, fmaxf(acc[nt][2], acc[nt][3]));
        }
        mx0 = fmaxf(mx0, __shfl_xor_sync(0xffffffffu, mx0, 1));
        mx0 = fmaxf(mx0, __shfl_xor_sync(0xffffffffu, mx0, 2));
        mx1 = fmaxf(mx1, __shfl_xor_sync(0xffffffffu, mx1, 1));
        mx1 = fmaxf(mx1, __shfl_xor_sync(0xffffffffu, mx1, 2));
        float mn0 = fmaxf(m0, mx0), mn1 = fmaxf(m1, mx1);
        float cr0 = __expf(m0 - mn0), cr1 = __expf(m1 - mn1);
        float rs0 = 0.f, rs1 = 0.f;
#pragma unroll
        for (int nt = 0; nt < 8; nt++) {
            acc[nt][0] = __expf(acc[nt][0] - mn0);
            acc[nt][1] = __expf(acc[nt][1] - mn0);
            acc[nt][2] = __expf(acc[nt][2] - mn1);
            acc[nt][3] = __expf(acc[nt][3] - mn1);
            rs0 += acc[nt][0] + acc[nt][1];
            rs1 += acc[nt][2] + acc[nt][3];
        }
        rs0 += __shfl_xor_sync(0xffffffffu, rs0, 1);
        rs0 += __shfl_xor_sync(0xffffffffu, rs0, 2);
        rs1 += __shfl_xor_sync(0xffffffffu, rs1, 1);
        rs1 += __shfl_xor_sync(0xffffffffu, rs1, 2);
        l0 = l0 * cr0 + rs0; m0 = mn0;
        l1 = l1 * cr1 + rs1; m1 = mn1;
#pragma unroll
        for (int nt = 0; nt < 8; nt++) {
            O[nt][0] *= cr0; O[nt][1] *= cr0;
            O[nt][2] *= cr1; O[nt][3] *= cr1;
        }

        // ---- O += P V, term-ordered ----
#pragma unroll
        for (int kc = 0; kc < 4; kc++) {
            u32 pah[4], pal[4];
            {
                float* pa = acc[kc * 2];
                float* pb = acc[kc * 2 + 1];
                pah[0] = prmt_hi(pa[0], pa[1]);
                pah[1] = prmt_hi(pa[2], pa[3]);
                pah[2] = prmt_hi(pb[0], pb[1]);
                pah[3] = prmt_hi(pb[2], pb[3]);
                pal[0] = prmt_hi(pa[0] - trunc_hi(pa[0]), pa[1] - trunc_hi(pa[1]));
                pal[1] = prmt_hi(pa[2] - trunc_hi(pa[2]), pa[3] - trunc_hi(pa[3]));
                pal[2] = prmt_hi(pb[0] - trunc_hi(pb[0]), pb[1] - trunc_hi(pb[1]));
                pal[3] = prmt_hi(pb[2] - trunc_hi(pb[2]), pb[3] - trunc_hi(pb[3]));
            }
            u32 vbh[4][4], vbl[4][4];
#pragma unroll
            for (int dp = 0; dp < 4; dp++) {
                int row = kc * 16 + ((lane >> 3) & 1) * 8 + (lane & 7);
                int ch = dp * 2 + (lane >> 4);
                u32 a = Vhs + row * 128 + ((u32)(ch ^ (row & 7)) << 4);
                ldm_x4_t(a, vbh[dp]);
                ldm_x4_t(a + 8192, vbl[dp]);
            }
#pragma unroll
            for (int dp = 0; dp < 4; dp++)
#pragma unroll
                for (int hh = 0; hh < 2; hh++)
                    mma16816(O[dp * 2 + hh], pah, &vbh[dp][hh * 2]);
#pragma unroll
            for (int dp = 0; dp < 4; dp++)
#pragma unroll
                for (int hh = 0; hh < 2; hh++)
                    mma16816(O[dp * 2 + hh], pal, &vbh[dp][hh * 2]);
#pragma unroll
            for (int dp = 0; dp < 4; dp++)
#pragma unroll
                for (int hh = 0; hh < 2; hh++)
                    mma16816(O[dp * 2 + hh], pah, &vbl[dp][hh * 2]);
        }
        __syncthreads();
    }

    // ---- epilogue: normalize + gate + bf16 hi/lo split ----
    l0 += __shfl_xor_sync(0xffffffffu, l0, 1);
    l0 += __shfl_xor_sync(0xffffffffu, l0, 2);
    l1 += __shfl_xor_sync(0xffffffffu, l1, 1);
    l1 += __shfl_xor_sync(0xffffffffu, l1, 2);
    // rs was already quad-reduced each tile; compensate uniform 4x.
    l0 *= 0.25f; l1 *= 0.25f;
    float inv0 = 1.f / l0, inv1 = 1.f / l1;
    const int rg0 = i0 + w * 16 + (lane >> 2);
    const int cb = h * 64 + 2 * (lane & 3);
#pragma unroll
    for (int nt = 0; nt < 8; nt++) {
        int c = cb + nt * 8;
        float2 ga = *(const float2*)(g_g + (size_t)rg0 * 1024 + c);
        float2 gb = *(const float2*)(g_g + (size_t)(rg0 + 8) * 1024 + c);
        float o0 = O[nt][0] * inv0 * ga.x;
        float o1 = O[nt][1] * inv0 * ga.y;
        float o2 = O[nt][2] * inv1 * gb.x;
        float o3 = O[nt][3] * inv1 * gb.y;
        *(u32*)(g_ot_hi + (size_t)rg0 * 1024 + c) = prmt_hi(o0, o1);
        *(u32*)(g_ot_hi + (size_t)(rg0 + 8) * 1024 + c) = prmt_hi(o2, o3);
        *(u32*)(g_ot_lo + (size_t)rg0 * 1024 + c) =
            pkbf2(__float2bfloat16(o0 - trunc_hi(o0)), __float2bfloat16(o1 - trunc_hi(o1)));
        *(u32*)(g_ot_lo + (size_t)(rg0 + 8) * 1024 + c) =
            pkbf2(__float2bfloat16(o2 - trunc_hi(o2)), __float2bfloat16(o3 - trunc_hi(o3)));
    }
}

// ---------------- launch ----------------------------------------------------
extern "C" void kernel_launch(void* const* d_in, const int* in_sizes, int n_in,
                              void* d_out, int out_size) {
    const float* s    = (const float*)d_in[0];
    const float* kin  = (const float*)d_in[1];
    const float* mask = (const float*)d_in[2];
    const float* bias = (const float*)d_in[3];
    const float* Wq   = (const float*)d_in[4];
    const float* bq   = (const float*)d_in[5];
    const float* Wk   = (const float*)d_in[6];
    const float* Wv   = (const float*)d_in[7];
    const float* Wg   = (const float*)d_in[8];
    const float* Wo   = (const float*)d_in[9];
    const float* Wz   = (const float*)d_in[10];
    float* out = (float*)d_out;

    static cudaStream_t zstream = nullptr;
    static cudaEvent_t ev_fork = nullptr, ev_join = nullptr;
    if (zstream == nullptr) {
        cudaStreamCreateWithFlags(&zstream, cudaStreamNonBlocking);
        cudaEventCreateWithFlags(&ev_fork, cudaEventDisableTiming);
        cudaEventCreateWithFlags(&ev_join, cudaEventDisableTiming);
    }

    cudaFuncSetAttribute(proj_tc_kernel, cudaFuncAttributeMaxDynamicSharedMemorySize, 131072);
    cudaFuncSetAttribute(out_tc_kernel,  cudaFuncAttributeMaxDynamicSharedMemorySize, 131072);
    cudaFuncSetAttribute(attn_kernel,    cudaFuncAttributeMaxDynamicSharedMemorySize, 81920);
    cudaFuncSetAttribute(z_kernel,       cudaFuncAttributeMaxDynamicSharedMemorySize, 143360);

    // fork: z (issue/DRAM-bound) runs concurrently with split+proj (tensor-bound)
    cudaEventRecord(ev_fork, 0);
    cudaStreamWaitEvent(zstream, ev_fork, 0);
    z_kernel<<<1024, 256, 143360, zstream>>>(bias, Wz, mask);
    cudaEventRecord(ev_join, zstream);

    split_kernel<<<dim3(1024, 7), 256>>>(s, kin, Wq, Wk, Wv, Wg, Wo);
    proj_tc_kernel<<<dim3(8, 8, 4), 256, 131072>>>(bq);

    cudaStreamWaitEvent(0, ev_join, 0);
    attn_kernel<<<dim3(16, 16), 128, 81920>>>();
    out_tc_kernel<<<dim3(8, 8, 2), 256, 131072>>>();
    out_add_kernel<<<1024, 256>>>(out);
}

// round 14
// speedup vs baseline: 2.4747x; 1.3639x over previous
#include <cuda_runtime.h>
#include <cuda_bf16.h>
#include <cstdint>
#include <math.h>

#define CS 1024
#define NH 16
#define HD 64

typedef unsigned int u32;

// ---------------- scratch (static device globals; no runtime allocation) ----
__device__ float g_g[1024 * 1024];
__device__ float g_z[16 * 1024 * 1024];   // [h][i][j]
__device__ float g_part[2][1024 * 1024];  // split-K partials for out GEMM

// bf16 hi/lo split operands for tensor-core GEMMs
__device__ __nv_bfloat16 g_s_hi[1024 * 1024],  g_s_lo[1024 * 1024];
__device__ __nv_bfloat16 g_ki_hi[1024 * 1024], g_ki_lo[1024 * 1024];
__device__ __nv_bfloat16 g_wq_hi[1024 * 1024], g_wq_lo[1024 * 1024];
__device__ __nv_bfloat16 g_wk_hi[1024 * 1024], g_wk_lo[1024 * 1024];
__device__ __nv_bfloat16 g_wv_hi[1024 * 1024], g_wv_lo[1024 * 1024];
__device__ __nv_bfloat16 g_wg_hi[1024 * 1024], g_wg_lo[1024 * 1024];
__device__ __nv_bfloat16 g_wo_hi[1024 * 1024], g_wo_lo[1024 * 1024];
__device__ __nv_bfloat16 g_ot_hi[1024 * 1024], g_ot_lo[1024 * 1024];
// q,k,v stored directly as bf16 hi/lo from projection epilogue
__device__ __nv_bfloat16 g_qh[1024 * 1024], g_ql[1024 * 1024];
__device__ __nv_bfloat16 g_kh[1024 * 1024], g_kl[1024 * 1024];
__device__ __nv_bfloat16 g_vh[1024 * 1024], g_vl[1024 * 1024];

// ---------------- helpers ---------------------------------------------------
__device__ __forceinline__ u32 smem_u32(const void* p) {
    u32 a;
    asm("{ .reg .u64 t; cvta.to.shared.u64 t, %1; cvt.u32.u64 %0, t; }" : "=r"(a) : "l"(p));
    return a;
}
__device__ __forceinline__ void ldm_x4(u32 addr, u32* r) {
    asm volatile("ldmatrix.sync.aligned.m8n8.x4.shared.b16 {%0,%1,%2,%3}, [%4];"
                 : "=r"(r[0]), "=r"(r[1]), "=r"(r[2]), "=r"(r[3]) : "r"(addr));
}
__device__ __forceinline__ void ldm_x4_t(u32 addr, u32* r) {
    asm volatile("ldmatrix.sync.aligned.m8n8.x4.trans.shared.b16 {%0,%1,%2,%3}, [%4];"
                 : "=r"(r[0]), "=r"(r[1]), "=r"(r[2]), "=r"(r[3]) : "r"(addr));
}
__device__ __forceinline__ void mma16816(float* c, const u32* a, const u32* b) {
    asm volatile(
        "mma.sync.aligned.m16n8k16.row.col.f32.bf16.bf16.f32 "
        "{%0,%1,%2,%3},{%4,%5,%6,%7},{%8,%9},{%0,%1,%2,%3};"
        : "+f"(c[0]), "+f"(c[1]), "+f"(c[2]), "+f"(c[3])
        : "r"(a[0]), "r"(a[1]), "r"(a[2]), "r"(a[3]), "r"(b[0]), "r"(b[1]));
}
__device__ __forceinline__ u32 pkbf2(__nv_bfloat16 a, __nv_bfloat16 b) {
    __nv_bfloat162 t = __halves2bfloat162(a, b);
    return *(u32*)&t;
}
__device__ __forceinline__ u32 prmt_hi(float a, float b) {
    u32 r;
    asm("prmt.b32 %0, %1, %2, 0x7632;"
        : "=r"(r) : "r"(__float_as_uint(a)), "r"(__float_as_uint(b)));
    return r;
}
__device__ __forceinline__ float trunc_hi(float a) {
    return __uint_as_float(__float_as_uint(a) & 0xFFFF0000u);
}
__device__ __forceinline__ void cpa16(u32 dst, const void* src) {
    asm volatile("cp.async.cg.shared.global [%0], [%1], 16;" :: "r"(dst), "l"(src));
}
#define CPA_COMMIT() asm volatile("cp.async.commit_group;" ::: "memory")
#define CPA_WAIT(n)  asm volatile("cp.async.wait_group %0;" :: "n"(n) : "memory")

// ---------------- fp32 -> bf16 hi/lo split ----------------------------------
__global__ __launch_bounds__(256) void split_kernel(const float* __restrict__ s,
                                                    const float* __restrict__ kin,
                                                    const float* __restrict__ wq,
                                                    const float* __restrict__ wk,
                                                    const float* __restrict__ wv,
                                                    const float* __restrict__ wg,
                                                    const float* __restrict__ wo) {
    const float* src;
    __nv_bfloat16 *dh, *dl;
    switch (blockIdx.y) {
        case 0: src = s;   dh = g_s_hi;  dl = g_s_lo;  break;
        case 1: src = kin; dh = g_ki_hi; dl = g_ki_lo; break;
        case 2: src = wq;  dh = g_wq_hi; dl = g_wq_lo; break;
        case 3: src = wk;  dh = g_wk_hi; dl = g_wk_lo; break;
        case 4: src = wv;  dh = g_wv_hi; dl = g_wv_lo; break;
        case 5: src = wg;  dh = g_wg_hi; dl = g_wg_lo; break;
        default: src = wo; dh = g_wo_hi; dl = g_wo_lo; break;
    }
    size_t i = ((size_t)blockIdx.x * 256 + threadIdx.x) * 4;
    float4 v = *(const float4*)(src + i);
    __nv_bfloat16 h0 = __float2bfloat16(v.x), h1 = __float2bfloat16(v.y);
    __nv_bfloat16 h2 = __float2bfloat16(v.z), h3 = __float2bfloat16(v.w);
    __nv_bfloat16 l0 = __float2bfloat16(v.x - __bfloat162float(h0));
    __nv_bfloat16 l1 = __float2bfloat16(v.y - __bfloat162float(h1));
    __nv_bfloat16 l2 = __float2bfloat16(v.z - __bfloat162float(h2));
    __nv_bfloat16 l3 = __float2bfloat16(v.w - __bfloat162float(h3));
    *(uint2*)(dh + i) = make_uint2(pkbf2(h0, h1), pkbf2(h2, h3));
    *(uint2*)(dl + i) = make_uint2(pkbf2(l0, l1), pkbf2(l2, l3));
}

// ---------------- pipelined HMMA GEMM tile: C[128,128] = A * B^T ------------
__device__ __forceinline__ void gemm_stage_ld(char* smem, int stage,
                                              const __nv_bfloat16* Ah,
                                              const __nv_bfloat16* Al,
                                              const __nv_bfloat16* Bh,
                                              const __nv_bfloat16* Bl,
                                              int bm0, int bn0, int kt, int tid) {
    const u32 sb = smem_u32(smem) + stage * 65536;
#pragma unroll
    for (int op = 0; op < 4; op++) {
        const __nv_bfloat16* src = (op == 0) ? Ah : (op == 1) ? Al : (op == 2) ? Bh : Bl;
        const int r0 = (op < 2) ? bm0 : bn0;
        const u32 d0 = sb + op * 16384;
#pragma unroll
        for (int u = 0; u < 4; u++) {
            int lin = tid + u * 256;
            int row = lin >> 3, ch = lin & 7;
            u32 sw = (u32)(row * 128) + ((u32)(ch ^ (row & 7)) << 4);
            cpa16(d0 + sw, src + (size_t)(r0 + row) * 1024 + kt * 64 + (ch << 3));
        }
    }
}

template <int MODE>
__device__ __forceinline__ void hmma_tile(const __nv_bfloat16* __restrict__ Ah,
                                          const __nv_bfloat16* __restrict__ Al,
                                          const __nv_bfloat16* __restrict__ Bh,
                                          const __nv_bfloat16* __restrict__ Bl,
                                          float* __restrict__ C,
                                          __nv_bfloat16* __restrict__ Ch,
                                          __nv_bfloat16* __restrict__ Cl,
                                          const float* __restrict__ bias,
                                          int bm0, int bn0, int kt0, int ktn) {
    extern __shared__ char smem[];
    const int tid = threadIdx.x;
    const int lane = tid & 31, wid = tid >> 5;
    const int wm = wid & 1, wn = wid >> 1;          // 2 x 4 warp grid
    const u32 sbase = smem_u32(smem);

    float acc[4][4][4];
#pragma unroll
    for (int mt = 0; mt < 4; mt++)
#pragma unroll
        for (int nt = 0; nt < 4; nt++)
#pragma unroll
            for (int e = 0; e < 4; e++) acc[mt][nt][e] = 0.f;

    gemm_stage_ld(smem, 0, Ah, Al, Bh, Bl, bm0, bn0, kt0, tid);
    CPA_COMMIT();

    for (int i = 0; i < ktn; i++) {
        if (i + 1 < ktn) {
            gemm_stage_ld(smem, (i + 1) & 1, Ah, Al, Bh, Bl, bm0, bn0, kt0 + i + 1, tid);
            CPA_COMMIT();
            CPA_WAIT(1);
        } else {
            CPA_WAIT(0);
        }
        __syncthreads();
        const u32 st = sbase + (u32)(i & 1) * 65536;

#pragma unroll
        for (int ks = 0; ks < 4; ks++) {
            u32 ah[4][4], al[4][4], bh[2][4], bl[2][4];
#pragma unroll
            for (int mt = 0; mt < 4; mt++) {
                int row = wm * 64 + mt * 16 + (lane & 15);
                int ch = ks * 2 + (lane >> 4);
                u32 addr = st + row * 128 + ((u32)(ch ^ (row & 7)) << 4);
                ldm_x4(addr, ah[mt]);
                ldm_x4(addr + 16384, al[mt]);
            }
#pragma unroll
            for (int nh = 0; nh < 2; nh++) {
                int row = wn * 32 + nh * 16 + (lane & 7) + ((lane >> 4) << 3);
                int ch = ks * 2 + ((lane >> 3) & 1);
                u32 addr = st + 32768 + row * 128 + ((u32)(ch ^ (row & 7)) << 4);
                ldm_x4(addr, bh[nh]);
                ldm_x4(addr + 16384, bl[nh]);
            }
#pragma unroll
            for (int mt = 0; mt < 4; mt++)
#pragma unroll
                for (int nt = 0; nt < 4; nt++)
                    mma16816(acc[mt][nt], ah[mt], &bh[nt >> 1][(nt & 1) * 2]);
#pragma unroll
            for (int mt = 0; mt < 4; mt++)
#pragma unroll
                for (int nt = 0; nt < 4; nt++)
                    mma16816(acc[mt][nt], ah[mt], &bl[nt >> 1][(nt & 1) * 2]);
#pragma unroll
            for (int mt = 0; mt < 4; mt++)
#pragma unroll
                for (int nt = 0; nt < 4; nt++)
                    mma16816(acc[mt][nt], al[mt], &bh[nt >> 1][(nt & 1) * 2]);
        }
        __syncthreads();
    }

#pragma unroll
    for (int mt = 0; mt < 4; mt++) {
        int r0 = bm0 + wm * 64 + mt * 16 + (lane >> 2);
#pragma unroll
        for (int nt = 0; nt < 4; nt++) {
            int c0 = bn0 + wn * 32 + nt * 8 + (lane & 3) * 2;
            float v0 = acc[mt][nt][0], v1 = acc[mt][nt][1];
            float v2 = acc[mt][nt][2], v3 = acc[mt][nt][3];
            if (MODE == 1) {
                float b0 = bias[c0], b1 = bias[c0 + 1];
                v0 += b0; v1 += b1; v2 += b0; v3 += b1;
            }
            if (MODE == 2) {
                v0 = 1.f / (1.f + __expf(-v0)); v1 = 1.f / (1.f + __expf(-v1));
                v2 = 1.f / (1.f + __expf(-v2)); v3 = 1.f / (1.f + __expf(-v3));
            }
            if (MODE == 0 || MODE == 2) {
                *(float2*)(C + (size_t)r0 * 1024 + c0) = make_float2(v0, v1);
                *(float2*)(C + (size_t)(r0 + 8) * 1024 + c0) = make_float2(v2, v3);
            } else {
                *(u32*)(Ch + (size_t)r0 * 1024 + c0) = prmt_hi(v0, v1);
                *(u32*)(Ch + (size_t)(r0 + 8) * 1024 + c0) = prmt_hi(v2, v3);
                *(u32*)(Cl + (size_t)r0 * 1024 + c0) =
                    pkbf2(__float2bfloat16(v0 - trunc_hi(v0)), __float2bfloat16(v1 - trunc_hi(v1)));
                *(u32*)(Cl + (size_t)(r0 + 8) * 1024 + c0) =
                    pkbf2(__float2bfloat16(v2 - trunc_hi(v2)), __float2bfloat16(v3 - trunc_hi(v3)));
            }
        }
    }
}

// ---------------- fused projections q,k,v,g (HMMA, pipelined) ---------------
__global__ __launch_bounds__(256) void proj_tc_kernel(const float* __restrict__ bq) {
    const int bm0 = blockIdx.y * 128, bn0 = blockIdx.x * 128;
    switch (blockIdx.z) {
        case 0: hmma_tile<1>(g_s_hi, g_s_lo, g_wq_hi, g_wq_lo, nullptr, g_qh, g_ql, bq, bm0, bn0, 0, 16); break;
        case 1: hmma_tile<3>(g_ki_hi, g_ki_lo, g_wk_hi, g_wk_lo, nullptr, g_kh, g_kl, nullptr, bm0, bn0, 0, 16); break;
        case 2: hmma_tile<3>(g_ki_hi, g_ki_lo, g_wv_hi, g_wv_lo, nullptr, g_vh, g_vl, nullptr, bm0, bn0, 0, 16); break;
        default: hmma_tile<2>(g_s_hi, g_s_lo, g_wg_hi, g_wg_lo, g_g, nullptr, nullptr, nullptr, bm0, bn0, 0, 16); break;
    }
}

// ---------------- output GEMM: out = (g*o) @ Wo^T (split-K2) ----------------
__global__ __launch_bounds__(256) void out_tc_kernel() {
    const int kz = blockIdx.z;
    hmma_tile<0>(g_ot_hi, g_ot_lo, g_wo_hi, g_wo_lo, g_part[kz], nullptr, nullptr, nullptr,
                 blockIdx.y * 128, blockIdx.x * 128, kz * 8, 8);
}
__global__ __launch_bounds__(256) void out_add_kernel(float* __restrict__ out) {
    size_t i = ((size_t)blockIdx.x * 256 + threadIdx.x) * 4;
    float4 a = *(const float4*)(g_part[0] + i);
    float4 b = *(const float4*)(g_part[1] + i);
    *(float4*)(out + i) = make_float4(a.x + b.x, a.y + b.y, a.z + b.z, a.w + b.w);
}

// ---------------- tensor-core pair-bias z[h][i][j] + mask -------------------
// z = bias[1M,128] @ Wz[128,16], 3-term bf16 split with in-register fp32->hi/lo
// conversion (bias stays fp32 in smem; only one DRAM pass over 512 MB).
// 1024 CTAs x 256 thr; each CTA: 8 tiles of 128 pairs, cp.async double-buffered.
#define ZROW 132
#define ZTILE (128 * ZROW)
__device__ __forceinline__ void ztc_stage(u32 sb, int stage, const float* __restrict__ bias,
                                          size_t row0, int tid) {
    const u32 base = sb + (u32)stage * (ZTILE * 4);
#pragma unroll
    for (int u = 0; u < 16; u++) {
        int lin = tid + u * 256;
        int row = lin >> 5, c4 = lin & 31;
        cpa16(base + (u32)(row * ZROW + c4 * 4) * 4, bias + (row0 + row) * 128 + c4 * 4);
    }
}

__global__ __launch_bounds__(256) void z_kernel(const float* __restrict__ bias,
                                                const float* __restrict__ Wz,
                                                const float* __restrict__ mask) {
    extern __shared__ float zsm[];
    float* wz = zsm + 2 * ZTILE;
    const int tid = threadIdx.x, lane = tid & 31, w = tid >> 5;
    const u32 sb = smem_u32(zsm);
    const size_t p0 = (size_t)blockIdx.x * 1024;

    for (int i = tid; i < 2048; i += 256) wz[i] = Wz[i];
    ztc_stage(sb, 0, bias, p0, tid);
    CPA_COMMIT();
    __syncthreads();   // wz visible

    // build Wz B-fragments (n8k16, col-major B): b0 = (k=2t+{0,1}, n=g), b1 = k+8
    const int t = lane & 3, g = lane >> 2;
    u32 bh[8][2][2], bl[8][2][2];
#pragma unroll
    for (int ks = 0; ks < 8; ks++)
#pragma unroll
        for (int nt = 0; nt < 2; nt++) {
            int h = nt * 8 + g;
            int k0 = ks * 16 + 2 * t;
#pragma unroll
            for (int half = 0; half < 2; half++) {
                float w0 = wz[(k0 + half * 8) * 16 + h];
                float w1 = wz[(k0 + half * 8 + 1) * 16 + h];
                bh[ks][nt][half] = prmt_hi(w0, w1);
                bl[ks][nt][half] = pkbf2(__float2bfloat16(w0 - trunc_hi(w0)),
                                         __float2bfloat16(w1 - trunc_hi(w1)));
            }
        }

    for (int tile = 0; tile < 8; tile++) {
        if (tile + 1 < 8) {
            ztc_stage(sb, (tile + 1) & 1, bias, p0 + (size_t)(tile + 1) * 128, tid);
            CPA_COMMIT();
            CPA_WAIT(1);
        } else {
            CPA_WAIT(0);
        }
        __syncthreads();
        const float* buf = zsm + (tile & 1) * ZTILE;

        float acc[2][4];
#pragma unroll
        for (int nt = 0; nt < 2; nt++)
#pragma unroll
            for (int e = 0; e < 4; e++) acc[nt][e] = 0.f;

        const int r0 = w * 16 + g;
#pragma unroll
        for (int ks = 0; ks < 8; ks++) {
            int k0 = ks * 16 + 2 * t;
            u32 ah[4], al[4];
#pragma unroll
            for (int fi = 0; fi < 4; fi++) {
                int rr = r0 + ((fi & 1) << 3);     // a0:(r,k) a1:(r+8,k) a2:(r,k+8) a3:(r+8,k+8)
                int cc = k0 + ((fi >> 1) << 3);
                float2 f = *(const float2*)&buf[rr * ZROW + cc];
                ah[fi] = prmt_hi(f.x, f.y);
                al[fi] = pkbf2(__float2bfloat16(f.x - trunc_hi(f.x)),
                               __float2bfloat16(f.y - trunc_hi(f.y)));
            }
#pragma unroll
            for (int nt = 0; nt < 2; nt++) {
                mma16816(acc[nt], ah, bh[ks][nt]);
                mma16816(acc[nt], ah, bl[ks][nt]);
                mma16816(acc[nt], al, bh[ks][nt]);
            }
        }

        // store (C frag: rows r0, r0+8; cols nt*8 + 2t, +1) with mask folded in
        int jr = tile * 128 + r0;                  // == pair & 1023 (p0 multiple of 1024)
        float m0 = (1.f - mask[jr]) * (-1000000.f);
        float m1 = (1.f - mask[jr + 8]) * (-1000000.f);
        size_t pr0 = p0 + (size_t)jr, pr1 = pr0 + 8;
#pragma unroll
        for (int nt = 0; nt < 2; nt++) {
            int hc = nt * 8 + 2 * t;
            g_z[(size_t)hc * 1048576 + pr0]       = acc[nt][0] + m0;
            g_z[(size_t)(hc + 1) * 1048576 + pr0] = acc[nt][1] + m0;
            g_z[(size_t)hc * 1048576 + pr1]       = acc[nt][2] + m1;
            g_z[(size_t)(hc + 1) * 1048576 + pr1] = acc[nt][3] + m1;
        }
        __syncthreads();   // buffer free for restage
    }
}

// ---------------- HMMA flash attention (pipelined, BM=64, 2 CTA/SM) ---------
__device__ __forceinline__ void attn_ldkv(char* smc, int stage, int j0g, int h, int tid) {
    const u32 base = smem_u32(smc) + 16384 + stage * 32768;
#pragma unroll
    for (int u = 0; u < 4; u++) {
        int lin = tid + u * 128;
        int row = lin >> 3, ch = lin & 7;
        u32 sw = (u32)(row * 128) + ((u32)(ch ^ (row & 7)) << 4);
        size_t go = (size_t)(j0g + row) * 2048 + h * 128 + (ch << 4);
        cpa16(base + sw,         (const char*)g_kh + go);
        cpa16(base + 8192 + sw,  (const char*)g_kl + go);
        cpa16(base + 16384 + sw, (const char*)g_vh + go);
        cpa16(base + 24576 + sw, (const char*)g_vl + go);
    }
}

__global__ __launch_bounds__(128) void attn_kernel() {
    extern __shared__ char smc[];
    const int tid = threadIdx.x, lane = tid & 31, w = tid >> 5;
    const int h = blockIdx.y;
    const int i0 = blockIdx.x * 64;
    const u32 sb = smem_u32(smc);
    const u32 Qhs = sb;

#pragma unroll
    for (int u = 0; u < 4; u++) {
        int lin = tid + u * 128;
        int row = lin >> 3, ch = lin & 7;
        u32 sw16 = ((u32)(ch ^ (row & 7))) << 4;
        size_t go = (size_t)(i0 + row) * 2048 + h * 128 + (ch << 4);
        *(uint4*)(smc + row * 128 + sw16) = *(const uint4*)((const char*)g_qh + go);
        *(uint4*)(smc + 8192 + row * 128 + sw16) = *(const uint4*)((const char*)g_ql + go);
    }
    attn_ldkv(smc, 0, 0, h, tid);
    CPA_COMMIT();
    __syncthreads();

    u32 qh[4][4], ql[4][4];
    {
        int row = w * 16 + ((lane >> 3) & 1) * 8 + (lane & 7);
        u32 rbase = Qhs + row * 128;
#pragma unroll
        for (int kc = 0; kc < 4; kc++) {
            int ch = kc * 2 + (lane >> 4);
            u32 a = rbase + ((u32)(ch ^ (row & 7)) << 4);
            ldm_x4(a, qh[kc]);
            ldm_x4(a + 8192, ql[kc]);
        }
    }

    float m0 = -1e30f, m1 = -1e30f, l0 = 0.f, l1 = 0.f;
    float O[8][4];
#pragma unroll
    for (int nt = 0; nt < 8; nt++)
#pragma unroll
        for (int e = 0; e < 4; e++) O[nt][e] = 0.f;

    const float* zbase = g_z + (size_t)h * 1048576 +
                         (size_t)(i0 + w * 16 + (lane >> 2)) * 1024 + 2 * (lane & 3);

    for (int jt = 0; jt < 16; jt++) {
        const int j0g = jt * 64;
        if (jt + 1 < 16) {
            attn_ldkv(smc, (jt + 1) & 1, j0g + 64, h, tid);
            CPA_COMMIT();
            CPA_WAIT(1);
        } else {
            CPA_WAIT(0);
        }
        __syncthreads();
        const u32 Khs = sb + 16384 + (u32)(jt & 1) * 32768;
        const u32 Vhs = Khs + 16384;

        float acc[8][4];
#pragma unroll
        for (int nt = 0; nt < 8; nt++)
#pragma unroll
            for (int e = 0; e < 4; e++) acc[nt][e] = 0.f;

#pragma unroll
        for (int kc = 0; kc < 4; kc++) {
            u32 kbh[4][4], kbl[4][4];
#pragma unroll
            for (int jp = 0; jp < 4; jp++) {
                int row = jp * 16 + (lane >> 4) * 8 + (lane & 7);
                int ch = kc * 2 + ((lane >> 3) & 1);
                u32 a = Khs + row * 128 + ((u32)(ch ^ (row & 7)) << 4);
                ldm_x4(a, kbh[jp]);
                ldm_x4(a + 8192, kbl[jp]);
            }
#pragma unroll
            for (int jp = 0; jp < 4; jp++)
#pragma unroll
                for (int hh = 0; hh < 2; hh++)
                    mma16816(acc[jp * 2 + hh], qh[kc], &kbh[jp][hh * 2]);
#pragma unroll
            for (int jp = 0; jp < 4; jp++)
#pragma unroll
                for (int hh = 0; hh < 2; hh++)
                    mma16816(acc[jp * 2 + hh], qh[kc], &kbl[jp][hh * 2]);
#pragma unroll
            for (int jp = 0; jp < 4; jp++)
#pragma unroll
                for (int hh = 0; hh < 2; hh++)
                    mma16816(acc[jp * 2 + hh], ql[kc], &kbh[jp][hh * 2]);
        }

        const float* z0 = zbase + j0g;
        const float* z1 = z0 + 8192;
        float mx0 = -1e30f, mx1 = -1e30f;
#pragma unroll
        for (int nt = 0; nt < 8; nt++) {
            float2 za = *(const float2*)(z0 + nt * 8);
            float2 zb = *(const float2*)(z1 + nt * 8);
            acc[nt][0] = acc[nt][0] * 0.125f + za.x;
            acc[nt][1] = acc[nt][1] * 0.125f + za.y;
            acc[nt][2] = acc[nt][2] * 0.125f + zb.x;
            acc[nt][3] = acc[nt][3] * 0.125f + zb.y;
            mx0 = fmaxf(mx0, fmaxf(acc[nt][0], acc[nt][1]));
            mx1 = fmaxf(mx1, fmaxf(acc[nt][2], acc[nt][3]));
        }
        mx0 = fmaxf(mx0, __shfl_xor_sync(0xffffffffu, mx0, 1));
        mx0 = fmaxf(mx0, __shfl_xor_sync(0xffffffffu, mx0, 2));
        mx1 = fmaxf(mx1, __shfl_xor_sync(0xffffffffu, mx1, 1));
        mx1 = fmaxf(mx1, __shfl_xor_sync(0xffffffffu, mx1, 2));
        float mn0 = fmaxf(m0, mx0), mn1 = fmaxf(m1, mx1);
        float cr0 = __expf(m0 - mn0), cr1 = __expf(m1 - mn1);
        float rs0 = 0.f, rs1 = 0.f;
#pragma unroll
        for (int nt = 0; nt < 8; nt++) {
            acc[nt][0] = __expf(acc[nt][0] - mn0);
            acc[nt][1] = __expf(acc[nt][1] - mn0);
            acc[nt][2] = __expf(acc[nt][2] - mn1);
            acc[nt][3] = __expf(acc[nt][3] - mn1);
            rs0 += acc[nt][0] + acc[nt][1];
            rs1 += acc[nt][2] + acc[nt][3];
        }
        rs0 += __shfl_xor_sync(0xffffffffu, rs0, 1);
        rs0 += __shfl_xor_sync(0xffffffffu, rs0, 2);
        rs1 += __shfl_xor_sync(0xffffffffu, rs1, 1);
        rs1 += __shfl_xor_sync(0xffffffffu, rs1, 2);
        l0 = l0 * cr0 + rs0; m0 = mn0;
        l1 = l1 * cr1 + rs1; m1 = mn1;
#pragma unroll
        for (int nt = 0; nt < 8; nt++) {
            O[nt][0] *= cr0; O[nt][1] *= cr0;
            O[nt][2] *= cr1; O[nt][3] *= cr1;
        }

#pragma unroll
        for (int kc = 0; kc < 4; kc++) {
            u32 pah[4], pal[4];
            {
                float* pa = acc[kc * 2];
                float* pb = acc[kc * 2 + 1];
                pah[0] = prmt_hi(pa[0], pa[1]);
                pah[1] = prmt_hi(pa[2], pa[3]);
                pah[2] = prmt_hi(pb[0], pb[1]);
                pah[3] = prmt_hi(pb[2], pb[3]);
                pal[0] = prmt_hi(pa[0] - trunc_hi(pa[0]), pa[1] - trunc_hi(pa[1]));
                pal[1] = prmt_hi(pa[2] - trunc_hi(pa[2]), pa[3] - trunc_hi(pa[3]));
                pal[2] = prmt_hi(pb[0] - trunc_hi(pb[0]), pb[1] - trunc_hi(pb[1]));
                pal[3] = prmt_hi(pb[2] - trunc_hi(pb[2]), pb[3] - trunc_hi(pb[3]));
            }
            u32 vbh[4][4], vbl[4][4];
#pragma unroll
            for (int dp = 0; dp < 4; dp++) {
                int row = kc * 16 + ((lane >> 3) & 1) * 8 + (lane & 7);
                int ch = dp * 2 + (lane >> 4);
                u32 a = Vhs + row * 128 + ((u32)(ch ^ (row & 7)) << 4);
                ldm_x4_t(a, vbh[dp]);
                ldm_x4_t(a + 8192, vbl[dp]);
            }
#pragma unroll
            for (int dp = 0; dp < 4; dp++)
#pragma unroll
                for (int hh = 0; hh < 2; hh++)
                    mma16816(O[dp * 2 + hh], pah, &vbh[dp][hh * 2]);
#pragma unroll
            for (int dp = 0; dp < 4; dp++)
#pragma unroll
                for (int hh = 0; hh < 2; hh++)
                    mma16816(O[dp * 2 + hh], pal, &vbh[dp][hh * 2]);
#pragma unroll
            for (int dp = 0; dp < 4; dp++)
#pragma unroll
                for (int hh = 0; hh < 2; hh++)
                    mma16816(O[dp * 2 + hh], pah, &vbl[dp][hh * 2]);
        }
        __syncthreads();
    }

    l0 += __shfl_xor_sync(0xffffffffu, l0, 1);
    l0 += __shfl_xor_sync(0xffffffffu, l0, 2);
    l1 += __shfl_xor_sync(0xffffffffu, l1, 1);
    l1 += __shfl_xor_sync(0xffffffffu, l1, 2);
    l0 *= 0.25f; l1 *= 0.25f;   // rs was quad-reduced per tile; undo uniform 4x
    float inv0 = 1.f / l0, inv1 = 1.f / l1;
    const int rg0 = i0 + w * 16 + (lane >> 2);
    const int cb = h * 64 + 2 * (lane & 3);
#pragma unroll
    for (int nt = 0; nt < 8; nt++) {
        int c = cb + nt * 8;
        float2 ga = *(const float2*)(g_g + (size_t)rg0 * 1024 + c);
        float2 gb = *(const float2*)(g_g + (size_t)(rg0 + 8) * 1024 + c);
        float o0 = O[nt][0] * inv0 * ga.x;
        float o1 = O[nt][1] * inv0 * ga.y;
        float o2 = O[nt][2] * inv1 * gb.x;
        float o3 = O[nt][3] * inv1 * gb.y;
        *(u32*)(g_ot_hi + (size_t)rg0 * 1024 + c) = prmt_hi(o0, o1);
        *(u32*)(g_ot_hi + (size_t)(rg0 + 8) * 1024 + c) = prmt_hi(o2, o3);
        *(u32*)(g_ot_lo + (size_t)rg0 * 1024 + c) =
            pkbf2(__float2bfloat16(o0 - trunc_hi(o0)), __float2bfloat16(o1 - trunc_hi(o1)));
        *(u32*)(g_ot_lo + (size_t)(rg0 + 8) * 1024 + c) =
            pkbf2(__float2bfloat16(o2 - trunc_hi(o2)), __float2bfloat16(o3 - trunc_hi(o3)));
    }
}

// ---------------- launch ----------------------------------------------------
extern "C" void kernel_launch(void* const* d_in, const int* in_sizes, int n_in,
                              void* d_out, int out_size) {
    const float* s    = (const float*)d_in[0];
    const float* kin  = (const float*)d_in[1];
    const float* mask = (const float*)d_in[2];
    const float* bias = (const float*)d_in[3];
    const float* Wq   = (const float*)d_in[4];
    const float* bq   = (const float*)d_in[5];
    const float* Wk   = (const float*)d_in[6];
    const float* Wv   = (const float*)d_in[7];
    const float* Wg   = (const float*)d_in[8];
    const float* Wo   = (const float*)d_in[9];
    const float* Wz   = (const float*)d_in[10];
    float* out = (float*)d_out;

    static cudaStream_t zstream = nullptr;
    static cudaEvent_t ev_fork = nullptr, ev_join = nullptr;
    if (zstream == nullptr) {
        cudaStreamCreateWithFlags(&zstream, cudaStreamNonBlocking);
        cudaEventCreateWithFlags(&ev_fork, cudaEventDisableTiming);
        cudaEventCreateWithFlags(&ev_join, cudaEventDisableTiming);
    }

    cudaFuncSetAttribute(proj_tc_kernel, cudaFuncAttributeMaxDynamicSharedMemorySize, 131072);
    cudaFuncSetAttribute(out_tc_kernel,  cudaFuncAttributeMaxDynamicSharedMemorySize, 131072);
    cudaFuncSetAttribute(attn_kernel,    cudaFuncAttributeMaxDynamicSharedMemorySize, 81920);
    cudaFuncSetAttribute(z_kernel,       cudaFuncAttributeMaxDynamicSharedMemorySize, 143360);

    // fork: z (DRAM-paced HMMA) concurrent with split+proj (tensor-bound)
    cudaEventRecord(ev_fork, 0);
    cudaStreamWaitEvent(zstream, ev_fork, 0);
    z_kernel<<<1024, 256, 143360, zstream>>>(bias, Wz, mask);
    cudaEventRecord(ev_join, zstream);

    split_kernel<<<dim3(1024, 7), 256>>>(s, kin, Wq, Wk, Wv, Wg, Wo);
    proj_tc_kernel<<<dim3(8, 8, 4), 256, 131072>>>(bq);

    cudaStreamWaitEvent(0, ev_join, 0);
    attn_kernel<<<dim3(16, 16), 128, 81920>>>();
    out_tc_kernel<<<dim3(8, 8, 2), 256, 131072>>>();
    out_add_kernel<<<1024, 256>>>(out);
}